// round 13
// baseline (speedup 1.0000x reference)
#include <cuda_runtime.h>
#include <cuda_fp16.h>
#include <math.h>
#include <stdint.h>

#define BB 8
#define TT 4096
#define DD 768
#define DI 1536
#define BT (BB*TT)
#define CH 128
#define NCH 32
#define EPS 1e-5f
#define WSB 2304                    // wscan blocks (BB*DD*DD/8/256)

// ---------------- scratch (device globals) ----------------------------------
__device__ __half g_xnh[(size_t)BT*DD];
__device__ __half g_pgh[(size_t)BT*2*DI];          // fused proj|gate output [BT,3072]
__device__ __half g_uh[(size_t)BT*DI];
__device__ __half g_oh[(size_t)BT*DD];
__device__ __half g_vh[(size_t)BT*DD];
__device__ __half g_readsh[(size_t)BT*DD];
__device__ __half g_wth[4718592];                  // fp16 weights
__device__ __half g_Wbh[(size_t)(NCH-1)*BB*DD*DD]; // fp16 W slots
__device__ __half g_vTs[(size_t)BB*DD*TT];         // fp16 v^T, gw-scaled
__device__ __half g_kT[(size_t)BB*DD*TT];          // fp16 shifted-keys^T
__device__ __half g_SMh[(size_t)BB*NCH*CH*CH];     // rescaled masked S (fp16)

#define W_PROJ 0
#define W_GATE 1179648
#define W_OUTP 2359296
#define W_WRIT 3538944
#define W_READ 4128768

// ---------------- small helpers ---------------------------------------------
__device__ __forceinline__ unsigned smem_u32(const void* p){
    return (unsigned)__cvta_generic_to_shared(p);
}
__device__ __forceinline__ void cpa16(unsigned s, const void* g){
    asm volatile("cp.async.cg.shared.global [%0], [%1], 16;" :: "r"(s), "l"(g));
}
__device__ __forceinline__ void mma16(float* c, const unsigned* a, const unsigned* b){
    asm volatile("mma.sync.aligned.m16n8k16.row.col.f32.f16.f16.f32 "
        "{%0,%1,%2,%3}, {%4,%5,%6,%7}, {%8,%9}, {%0,%1,%2,%3};"
        : "+f"(c[0]), "+f"(c[1]), "+f"(c[2]), "+f"(c[3])
        : "r"(a[0]), "r"(a[1]), "r"(a[2]), "r"(a[3]), "r"(b[0]), "r"(b[1]));
}
__device__ __forceinline__ void ldsm4(unsigned& r0, unsigned& r1, unsigned& r2, unsigned& r3,
                                      unsigned addr){
    asm volatile("ldmatrix.sync.aligned.m8n8.x4.shared.b16 {%0,%1,%2,%3}, [%4];"
        : "=r"(r0), "=r"(r1), "=r"(r2), "=r"(r3) : "r"(addr));
}

// ================= 64-wide K-tile, 3-stage, 1-sync GEMM machinery ===========
#define SW 36                       // words per 64-half row (32 + 4 pad)
#define STW (2*128*SW)              // words per stage (A + B)
#define DSM_BYTES (3*STW*4)         // 110592 B

__device__ __forceinline__ void ldh64(unsigned* S, const __half* src, int ldk, int tid){
    unsigned sb = smem_u32(S);
    #pragma unroll
    for (int s = 0; s < 4; s++){
        int q = tid + 256*s; int r = q>>3, c = q&7;
        cpa16(sb + (unsigned)(r*SW + c*4)*4u, src + (size_t)r*ldk + c*8);
    }
}

__device__ __forceinline__ void mma_tile64(unsigned Au, unsigned Bu,
                                           float (&acc)[4][4][4], int lane, int wm, int wn){
    int arow  = wm*64 + (lane & 15);
    int aoffw = (lane >> 4) << 2;
    int bcol0 = wn*32 + ((lane >> 4) << 3) + (lane & 7);
    int boffw = ((lane >> 3) & 1) << 2;
    #pragma unroll
    for (int kk2 = 0; kk2 < 32; kk2 += 8){
        unsigned a[4][4], b[2][4];
        #pragma unroll
        for (int mi = 0; mi < 4; mi++)
            ldsm4(a[mi][0], a[mi][1], a[mi][2], a[mi][3],
                  Au + (unsigned)(((arow + mi*16)*SW + kk2 + aoffw) * 4));
        #pragma unroll
        for (int p = 0; p < 2; p++)
            ldsm4(b[p][0], b[p][1], b[p][2], b[p][3],
                  Bu + (unsigned)(((bcol0 + p*16)*SW + kk2 + boffw) * 4));
        #pragma unroll
        for (int mi = 0; mi < 4; mi++){
            mma16(acc[mi][0], a[mi], &b[0][0]);
            mma16(acc[mi][1], a[mi], &b[0][2]);
            mma16(acc[mi][2], a[mi], &b[1][0]);
            mma16(acc[mi][3], a[mi], &b[1][2]);
        }
    }
}

// EPI: 2 inter (readsh += gp*acc, fp16 storage); 5 half store;
//      7 final (C = base1 + float(Ch) + alpha*acc, fp32 out).
// Requires K % 64 == 0, K >= 128.
template<int EPI>
__global__ void __launch_bounds__(256, 2)
gemm_h(const __half* __restrict__ A, const __half* __restrict__ Bw,
       float* __restrict__ C, __half* __restrict__ Ch, int K, int N,
       const float* __restrict__ base1, const float* __restrict__ base2,
       const float* __restrict__ sp)
{
    extern __shared__ unsigned dsm[];
    int tid = threadIdx.x, lane = tid&31, warp = tid>>5;
    int wm = warp>>2, wn = warp&3;
    int bn = blockIdx.x*128;
    size_t bm, aoff, boff, coff;
    if (EPI == 2){
        int z = blockIdx.z, b = z/(NCH-1), n = z%(NCH-1) + 1;
        aoff = ((size_t)b*TT + (size_t)n*CH)*DD;
        boff = ((size_t)(n-1)*BB + b)*(size_t)DD*DD;
        coff = aoff; bm = 0;
    } else { bm = (size_t)blockIdx.y*128; aoff = 0; boff = 0; coff = 0; }

    float acc[4][4][4];
    #pragma unroll
    for (int i=0;i<4;i++)
        #pragma unroll
        for(int j=0;j<4;j++)
            #pragma unroll
            for(int q=0;q<4;q++) acc[i][j][q]=0.f;

    const __half* Ag = A + aoff + bm*(size_t)K;
    const __half* Bg = Bw + boff + (size_t)bn*K;
    int nk = K >> 6;
    unsigned dsmu = smem_u32(dsm);

    ldh64(dsm,            Ag,      K, tid);
    ldh64(dsm + 128*SW,   Bg,      K, tid);
    asm volatile("cp.async.commit_group;" ::: "memory");
    ldh64(dsm + STW,          Ag + 64, K, tid);
    ldh64(dsm + STW + 128*SW, Bg + 64, K, tid);
    asm volatile("cp.async.commit_group;" ::: "memory");

    int cur = 0, nxt = 2;
    for (int t = 0; t < nk; t++){
        asm volatile("cp.async.wait_group 1;" ::: "memory");
        __syncthreads();
        if (t + 2 < nk){
            ldh64(dsm + nxt*STW,          Ag + (t+2)*64, K, tid);
            ldh64(dsm + nxt*STW + 128*SW, Bg + (t+2)*64, K, tid);
        }
        asm volatile("cp.async.commit_group;" ::: "memory");
        mma_tile64(dsmu + (unsigned)(cur*STW*4),
                   dsmu + (unsigned)((cur*STW + 128*SW)*4), acc, lane, wm, wn);
        cur = (cur == 2) ? 0 : cur + 1;
        nxt = (nxt == 2) ? 0 : nxt + 1;
    }

    int tg = lane&3, gid = lane>>2;
    float alpha = (EPI==7) ? expf(sp[0]) : 0.f;
    float lg = 0.f;
    if (EPI==2){
        float gamma = 1.f/(1.f+expf(-sp[0]));
        lg = logf(gamma);
    }
    #pragma unroll
    for (int mi=0;mi<4;mi++){
        float s0 = 0.f, s1 = 0.f;
        if (EPI==2){
            s0 = expf((float)(wm*64 + mi*16 + gid)*lg);
            s1 = expf((float)(wm*64 + mi*16 + gid + 8)*lg);
        }
        #pragma unroll
        for (int ni=0;ni<4;ni++){
            int row = (int)bm + wm*64 + mi*16 + gid;
            int col = bn + wn*32 + ni*8 + 2*tg;
            size_t i0 = coff + (size_t)row*N + col;
            size_t i1 = coff + (size_t)(row+8)*N + col;
            float a0 = acc[mi][ni][0], a1 = acc[mi][ni][1];
            float a2 = acc[mi][ni][2], a3 = acc[mi][ni][3];
            if (EPI == 5){
                *(__half2*)(Ch+i0) = __floats2half2_rn(a0, a1);
                *(__half2*)(Ch+i1) = __floats2half2_rn(a2, a3);
            } else if (EPI == 2){
                float2 c0 = __half22float2(*(__half2*)(Ch+i0));
                float2 c1 = __half22float2(*(__half2*)(Ch+i1));
                *(__half2*)(Ch+i0) = __floats2half2_rn(c0.x + s0*a0, c0.y + s0*a1);
                *(__half2*)(Ch+i1) = __floats2half2_rn(c1.x + s1*a2, c1.y + s1*a3);
            } else { // EPI==7
                float2 x0 = *(const float2*)(base1+i0);
                float2 x1 = *(const float2*)(base1+i1);
                float2 o0 = __half22float2(*(const __half2*)(Ch+i0));
                float2 o1 = __half22float2(*(const __half2*)(Ch+i1));
                *(float2*)(C+i0) = make_float2(x0.x+o0.x+alpha*a0, x0.y+o0.y+alpha*a1);
                *(float2*)(C+i1) = make_float2(x1.x+o1.x+alpha*a2, x1.y+o1.y+alpha*a3);
            }
        }
    }
}

// ================= 32-wide K-tile 2-stage machinery (scan kernels) ==========
#define SMH 20

__device__ __forceinline__ void ldh(unsigned* S, const __half* src, int ldk, int tid){
    unsigned sb = smem_u32(S);
    #pragma unroll
    for (int s = 0; s < 2; s++){
        int q = tid + 256*s; int r = q>>2, kc8 = (q&3)<<3;
        cpa16(sb + (unsigned)(r*SMH + (kc8>>1))*4u, src + (size_t)r*ldk + kc8);
    }
}

__device__ __forceinline__ void mma_tile_h(unsigned Au, unsigned Bu,
                                           float (&acc)[4][4][4], int lane, int wm, int wn){
    int arow  = wm*64 + (lane & 15);
    int aoffw = (lane >> 4) << 2;
    int bcol0 = wn*32 + ((lane >> 4) << 3) + (lane & 7);
    int boffw = ((lane >> 3) & 1) << 2;
    #pragma unroll
    for (int kk2 = 0; kk2 < 16; kk2 += 8){
        unsigned a[4][4], b[2][4];
        #pragma unroll
        for (int mi = 0; mi < 4; mi++)
            ldsm4(a[mi][0], a[mi][1], a[mi][2], a[mi][3],
                  Au + (unsigned)(((arow + mi*16)*SMH + kk2 + aoffw) * 4));
        #pragma unroll
        for (int p = 0; p < 2; p++)
            ldsm4(b[p][0], b[p][1], b[p][2], b[p][3],
                  Bu + (unsigned)(((bcol0 + p*16)*SMH + kk2 + boffw) * 4));
        #pragma unroll
        for (int mi = 0; mi < 4; mi++){
            mma16(acc[mi][0], a[mi], &b[0][0]);
            mma16(acc[mi][1], a[mi], &b[0][2]);
            mma16(acc[mi][2], a[mi], &b[1][0]);
            mma16(acc[mi][3], a[mi], &b[1][2]);
        }
    }
}

// ---------------- wscan body: grouped serial AXPY over fp16 slots -----------
__device__ void wscan_body(int bid, int tid, int s0, int cnt, const float* decay_p){
    const size_t n = (size_t)BB*DD*DD;
    size_t i = ((size_t)bid*256 + tid)*8;
    if (i >= n) return;
    float gamma = 1.f/(1.f+expf(-decay_p[0]));
    float gC = expf(128.f*logf(gamma));
    uint4 pv = *(const uint4*)(g_Wbh + (size_t)(s0-1)*n + i);
    float2 p[4];
    p[0] = __half22float2(*(__half2*)&pv.x);
    p[1] = __half22float2(*(__half2*)&pv.y);
    p[2] = __half22float2(*(__half2*)&pv.z);
    p[3] = __half22float2(*(__half2*)&pv.w);
    for (int j = 0; j < cnt; j++){
        uint4* cur = (uint4*)(g_Wbh + (size_t)(s0+j)*n + i);
        uint4 cv = *cur;
        float2 c[4];
        c[0] = __half22float2(*(__half2*)&cv.x);
        c[1] = __half22float2(*(__half2*)&cv.y);
        c[2] = __half22float2(*(__half2*)&cv.z);
        c[3] = __half22float2(*(__half2*)&cv.w);
        #pragma unroll
        for (int q = 0; q < 4; q++){ c[q].x += gC*p[q].x; c[q].y += gC*p[q].y; p[q] = c[q]; }
        *(__half2*)&cv.x = __floats2half2_rn(c[0].x, c[0].y);
        *(__half2*)&cv.y = __floats2half2_rn(c[1].x, c[1].y);
        *(__half2*)&cv.z = __floats2half2_rn(c[2].x, c[2].y);
        *(__half2*)&cv.w = __floats2half2_rn(c[3].x, c[3].y);
        *cur = cv;
    }
}

// ---------------- s_batch body: masked rescaled S (fp16) --------------------
__device__ void s_batch_body(unsigned* As0, unsigned* Bs0, int z, int tid,
                             const float* decay_p){
    int b = z/NCH, n = z%NCH;
    int lane = tid&31, warp = tid>>5, wm = warp>>2, wn = warp&3;
    float acc[4][4][4];
    #pragma unroll
    for (int i=0;i<4;i++)
        #pragma unroll
        for(int j=0;j<4;j++)
            #pragma unroll
            for(int q=0;q<4;q++) acc[i][j][q]=0.f;

    const __half* rb = g_oh + ((size_t)b*TT + (size_t)n*CH)*DD;
    const __half* kb = rb - DD;
    bool z0 = (n == 0);

    auto ldb = [&](unsigned* S, int k0){
        unsigned sb = smem_u32(S);
        #pragma unroll
        for (int s = 0; s < 2; s++){
            int q = tid + 256*s; int r = q>>2, kc8 = (q&3)<<3;
            if (z0 && r == 0){
                *(uint4*)(S + r*SMH + (kc8>>1)) = make_uint4(0,0,0,0);
            } else {
                cpa16(sb + (unsigned)(r*SMH + (kc8>>1))*4u, kb + (size_t)r*DD + k0 + kc8);
            }
        }
    };

    ldh(As0, rb, DD, tid);
    ldb(Bs0, 0);
    asm volatile("cp.async.commit_group;" ::: "memory");
    int nk = DD >> 5;
    for (int t = 0; t < nk; t++){
        int cur = t & 1;
        if (t + 1 < nk){
            ldh(As0 + (cur^1)*128*SMH, rb + (t+1)*32, DD, tid);
            ldb(Bs0 + (cur^1)*128*SMH, (t+1)*32);
            asm volatile("cp.async.commit_group;" ::: "memory");
            asm volatile("cp.async.wait_group 1;" ::: "memory");
        } else {
            asm volatile("cp.async.wait_group 0;" ::: "memory");
        }
        __syncthreads();
        mma_tile_h(smem_u32(As0 + cur*128*SMH), smem_u32(Bs0 + cur*128*SMH),
                   acc, lane, wm, wn);
        __syncthreads();
    }

    float gamma = 1.f/(1.f+expf(-decay_p[0]));
    float lg = logf(gamma);
    __half* smb = g_SMh + ((size_t)b*NCH + n)*CH*CH;
    int tg=lane&3, gid=lane>>2;
    #pragma unroll
    for (int mi=0;mi<4;mi++){
        int c0r = wm*64 + mi*16 + gid;
        float sc0 = expf((float)(c0r - 128)*lg);
        float sc1 = expf((float)(c0r - 120)*lg);
        #pragma unroll
        for (int ni=0;ni<4;ni++){
            int e0c = wn*32 + ni*8 + 2*tg;
            float v0 = (c0r   > e0c  ) ? sc0*acc[mi][ni][0] : 0.f;
            float v1 = (c0r   > e0c+1) ? sc0*acc[mi][ni][1] : 0.f;
            float v2 = (c0r+8 > e0c  ) ? sc1*acc[mi][ni][2] : 0.f;
            float v3 = (c0r+8 > e0c+1) ? sc1*acc[mi][ni][3] : 0.f;
            *(__half2*)(smb + (size_t)c0r*CH + e0c)     = __floats2half2_rn(v0, v1);
            *(__half2*)(smb + (size_t)(c0r+8)*CH + e0c) = __floats2half2_rn(v2, v3);
        }
    }
}

// ---------------- intra body: readsh = SM' @ vTs^T (fp16 only) --------------
__device__ void intra_body(unsigned* As0, unsigned* Bs0, int z, int bn, int tid){
    int b = z/NCH, n = z%NCH;
    int lane = tid&31, warp = tid>>5, wm = warp>>2, wn = warp&3;
    float acc[4][4][4];
    #pragma unroll
    for (int i=0;i<4;i++)
        #pragma unroll
        for(int j=0;j<4;j++)
            #pragma unroll
            for(int q=0;q<4;q++) acc[i][j][q]=0.f;

    const __half* Ag = g_SMh + ((size_t)b*NCH + n)*CH*CH;
    const __half* Bg = g_vTs + ((size_t)b*DD + bn)*TT + (size_t)n*CH;

    ldh(As0, Ag, CH, tid);
    ldh(Bs0, Bg, TT, tid);
    asm volatile("cp.async.commit_group;" ::: "memory");
    const int nk = CH >> 5;   // 4
    for (int t = 0; t < nk; t++){
        int cur = t & 1;
        if (t + 1 < nk){
            ldh(As0 + (cur^1)*128*SMH, Ag + (t+1)*32, CH, tid);
            ldh(Bs0 + (cur^1)*128*SMH, Bg + (t+1)*32, TT, tid);
            asm volatile("cp.async.commit_group;" ::: "memory");
            asm volatile("cp.async.wait_group 1;" ::: "memory");
        } else {
            asm volatile("cp.async.wait_group 0;" ::: "memory");
        }
        __syncthreads();
        mma_tile_h(smem_u32(As0 + cur*128*SMH), smem_u32(Bs0 + cur*128*SMH),
                   acc, lane, wm, wn);
        __syncthreads();
    }

    size_t ob = ((size_t)b*TT + (size_t)n*CH)*DD + bn;
    int tg=lane&3, gid=lane>>2;
    #pragma unroll
    for (int mi=0;mi<4;mi++){
        #pragma unroll
        for (int ni=0;ni<4;ni++){
            int row = wm*64 + mi*16 + gid;
            int col = wn*32 + ni*8 + 2*tg;
            size_t i0 = ob + (size_t)row*DD + col;
            size_t i1 = ob + (size_t)(row+8)*DD + col;
            *(__half2*)(g_readsh+i0) = __floats2half2_rn(acc[mi][ni][0], acc[mi][ni][1]);
            *(__half2*)(g_readsh+i1) = __floats2half2_rn(acc[mi][ni][2], acc[mi][ni][3]);
        }
    }
}

// ---------------- combined launches: scan GEMMs hidden under wscan ----------
__global__ void __launch_bounds__(256)
wscan_sbatch_k(const float* __restrict__ decay_p){
    __shared__ unsigned As[2*128*SMH], Bs[2*128*SMH];
    int tid = threadIdx.x;
    if ((int)blockIdx.x < BB*NCH)
        s_batch_body(As, Bs, blockIdx.x, tid, decay_p);
    else
        wscan_body(blockIdx.x - BB*NCH, tid, 1, 8, decay_p);
}
__global__ void __launch_bounds__(256)
wscan_intra_k(const float* __restrict__ decay_p){
    __shared__ unsigned As[2*128*SMH], Bs[2*128*SMH];
    int tid = threadIdx.x;
    if ((int)blockIdx.x < 6*BB*NCH){
        int q = blockIdx.x;
        intra_body(As, Bs, q/6, (q%6)*128, tid);
    } else {
        wscan_body(blockIdx.x - 6*BB*NCH, tid, 9, 8, decay_p);
    }
}
__global__ void wscan_h(int s0, int cnt, const float* __restrict__ decay_p){
    wscan_body(blockIdx.x, threadIdx.x, s0, cnt, decay_p);
}

// ---------------- u_batch (standalone, fp16 GEMM) ---------------------------
__global__ void __launch_bounds__(256)
u_batch_h(){
    __shared__ unsigned As[2][128*SMH], Bs[2][128*SMH];
    int z = blockIdx.z, b = z/(NCH-1), mch = z%(NCH-1);
    int bm = blockIdx.y*128, bn = blockIdx.x*128;
    int tid = threadIdx.x, lane = tid&31, warp = tid>>5;
    int wm = warp>>2, wn = warp&3;
    float acc[4][4][4];
    #pragma unroll
    for (int i=0;i<4;i++)
        #pragma unroll
        for(int j=0;j<4;j++)
            #pragma unroll
            for(int q=0;q<4;q++) acc[i][j][q]=0.f;

    const __half* Ag = g_vTs + ((size_t)b*DD + bm)*TT + (size_t)mch*CH;
    const __half* Bg = g_kT  + ((size_t)b*DD + bn)*TT + (size_t)mch*CH;

    ldh(As[0], Ag, TT, tid);
    ldh(Bs[0], Bg, TT, tid);
    asm volatile("cp.async.commit_group;" ::: "memory");
    const int nk = CH >> 5;
    for (int t = 0; t < nk; t++){
        int cur = t & 1;
        if (t + 1 < nk){
            ldh(As[cur^1], Ag + (t+1)*32, TT, tid);
            ldh(Bs[cur^1], Bg + (t+1)*32, TT, tid);
            asm volatile("cp.async.commit_group;" ::: "memory");
            asm volatile("cp.async.wait_group 1;" ::: "memory");
        } else {
            asm volatile("cp.async.wait_group 0;" ::: "memory");
        }
        __syncthreads();
        mma_tile_h(smem_u32(As[cur]), smem_u32(Bs[cur]), acc, lane, wm, wn);
        __syncthreads();
    }

    __half* Wout = g_Wbh + ((size_t)mch*BB + b)*(size_t)DD*DD;
    int tg = lane&3, gid = lane>>2;
    #pragma unroll
    for (int mi=0;mi<4;mi++){
        #pragma unroll
        for (int ni=0;ni<4;ni++){
            int row = bm + wm*64 + mi*16 + gid;
            int col = bn + wn*32 + ni*8 + 2*tg;
            *(__half2*)(Wout + (size_t)row*DD + col)     = __floats2half2_rn(acc[mi][ni][0], acc[mi][ni][1]);
            *(__half2*)(Wout + (size_t)(row+8)*DD + col) = __floats2half2_rn(acc[mi][ni][2], acc[mi][ni][3]);
        }
    }
}

// ---------------- transpose: build vT (gw-scaled) and shifted-keys^T --------
__global__ void tpose_k(const float* __restrict__ decay_p){
    __shared__ float s1[32][33], s2[32][33];
    int b = blockIdx.z, d0 = blockIdx.y*32, t0 = blockIdx.x*32;
    int tx = threadIdx.x, ty = threadIdx.y;      // 32 x 8
    float gamma = 1.f/(1.f+expf(-decay_p[0]));
    float lg = logf(gamma);
    const __half* vb = g_vh + (size_t)b*TT*DD;
    const __half* ob = g_oh + (size_t)b*TT*DD;
    #pragma unroll
    for (int i = 0; i < 4; i++){
        int tl = ty + 8*i;
        int t = t0 + tl;
        float gw = expf((float)(CH-1-(t&(CH-1)))*lg);
        s1[tl][tx] = __half2float(vb[(size_t)t*DD + d0 + tx]) * gw;
        s2[tl][tx] = (t == 0) ? 0.f : __half2float(ob[(size_t)(t-1)*DD + d0 + tx]);
    }
    __syncthreads();
    __half* vT = g_vTs + (size_t)b*DD*TT;
    __half* kT = g_kT  + (size_t)b*DD*TT;
    #pragma unroll
    for (int i = 0; i < 4; i++){
        int dl = ty + 8*i;
        vT[(size_t)(d0+dl)*TT + t0 + tx] = __float2half_rn(s1[tx][dl]);
        kT[(size_t)(d0+dl)*TT + t0 + tx] = __float2half_rn(s2[tx][dl]);
    }
}

// ---------------- rmsnorm (half out) ----------------------------------------
__global__ void rmsnorm_k(const float* __restrict__ x, const float* __restrict__ w) {
    int row = blockIdx.x;
    const float* xr = x + (size_t)row*DD;
    __half* o = g_xnh + (size_t)row*DD;
    float s = 0.f;
    for (int d = threadIdx.x; d < DD; d += blockDim.x) { float v = xr[d]; s += v*v; }
    __shared__ float red[32];
    for (int off = 16; off; off >>= 1) s += __shfl_down_sync(0xffffffffu, s, off);
    if ((threadIdx.x & 31) == 0) red[threadIdx.x >> 5] = s;
    __syncthreads();
    if (threadIdx.x < 32) {
        float t = (threadIdx.x < (blockDim.x >> 5)) ? red[threadIdx.x] : 0.f;
        for (int off = 16; off; off >>= 1) t += __shfl_down_sync(0xffffffffu, t, off);
        if (threadIdx.x == 0) red[0] = t;
    }
    __syncthreads();
    float scale = rsqrtf(red[0] / (float)DD + EPS);
    for (int d = threadIdx.x; d < DD; d += blockDim.x)
        o[d] = __float2half_rn(xr[d] * scale * w[d]);
}

// ---------------- fp32 -> fp16 convert (weights) ----------------------------
__global__ void f2h_k(const float* __restrict__ src, __half* __restrict__ dst, long n4){
    long i = (long)blockIdx.x*256 + threadIdx.x;
    if (i < n4){
        float4 v = ((const float4*)src)[i];
        ((__half2*)dst)[2*i]   = __floats2half2_rn(v.x, v.y);
        ((__half2*)dst)[2*i+1] = __floats2half2_rn(v.z, v.w);
    }
}

// ---------------- depthwise causal conv + silu gate (fused pg buffer) -------
__global__ void conv_gate_k(const float* __restrict__ cw, const float* __restrict__ cb) {
    long j4 = (long)blockIdx.x*blockDim.x + threadIdx.x;
    const long NV = (long)BT*DI/4;
    if (j4 >= NV) return;
    int e4 = (int)(j4 % (DI/4));
    long bl = j4 / (DI/4);
    int l = (int)(bl % TT);
    int e = e4*4;
    float4 acc = *(const float4*)(cb + e);
    #pragma unroll
    for (int jj = 0; jj < 4; jj++){
        int ll = l - 3 + jj;
        if (ll >= 0){
            const __half2* vp = (const __half2*)(g_pgh + (bl-(3-jj))*(2*DI) + e);
            float2 v01 = __half22float2(vp[0]);
            float2 v23 = __half22float2(vp[1]);
            acc.x += v01.x * cw[(e+0)*4+jj];
            acc.y += v01.y * cw[(e+1)*4+jj];
            acc.z += v23.x * cw[(e+2)*4+jj];
            acc.w += v23.y * cw[(e+3)*4+jj];
        }
    }
    const __half2* gp = (const __half2*)(g_pgh + bl*(2*DI) + DI + e);
    float2 g01 = __half22float2(gp[0]);
    float2 g23 = __half22float2(gp[1]);
    float rx = (acc.x/(1.f+expf(-acc.x))) * (g01.x/(1.f+expf(-g01.x)));
    float ry = (acc.y/(1.f+expf(-acc.y))) * (g01.y/(1.f+expf(-g01.y)));
    float rz = (acc.z/(1.f+expf(-acc.z))) * (g23.x/(1.f+expf(-g23.x)));
    float rw = (acc.w/(1.f+expf(-acc.w))) * (g23.y/(1.f+expf(-g23.y)));
    __half2* up = (__half2*)(g_uh + j4*4);
    up[0] = __floats2half2_rn(rx, ry);
    up[1] = __floats2half2_rn(rz, rw);
}

// ---------------- launch ----------------------------------------------------
extern "C" void kernel_launch(void* const* d_in, const int* in_sizes, int n_in,
                              void* d_out, int out_size) {
    const float* x          = (const float*)d_in[0];
    const float* norm_w     = (const float*)d_in[1];
    const float* proj_w     = (const float*)d_in[2];
    const float* gate_w     = (const float*)d_in[3];
    const float* conv_w     = (const float*)d_in[4];
    const float* conv_b     = (const float*)d_in[5];
    const float* out_proj_w = (const float*)d_in[6];
    const float* write_w    = (const float*)d_in[7];
    const float* read_w     = (const float*)d_in[8];
    const float* decay      = (const float*)d_in[9];
    const float* log_alpha  = (const float*)d_in[10];
    float* out = (float*)d_out;

    __half *xnh, *pgh, *uh, *oh, *vh, *readsh, *wth, *wbh;
    cudaGetSymbolAddress((void**)&xnh,    g_xnh);
    cudaGetSymbolAddress((void**)&pgh,    g_pgh);
    cudaGetSymbolAddress((void**)&uh,     g_uh);
    cudaGetSymbolAddress((void**)&oh,     g_oh);
    cudaGetSymbolAddress((void**)&vh,     g_vh);
    cudaGetSymbolAddress((void**)&readsh, g_readsh);
    cudaGetSymbolAddress((void**)&wth,    g_wth);
    cudaGetSymbolAddress((void**)&wbh,    g_Wbh);

    cudaFuncSetAttribute(gemm_h<2>, cudaFuncAttributeMaxDynamicSharedMemorySize, DSM_BYTES);
    cudaFuncSetAttribute(gemm_h<5>, cudaFuncAttributeMaxDynamicSharedMemorySize, DSM_BYTES);
    cudaFuncSetAttribute(gemm_h<7>, cudaFuncAttributeMaxDynamicSharedMemorySize, DSM_BYTES);

    // launches 0-2 (keeps the big fused GEMM at ncu capture idx 3)
    f2h_k<<<(294912+255)/256, 256>>>(proj_w, wth + W_PROJ, 294912);   // 0
    f2h_k<<<(294912+255)/256, 256>>>(gate_w, wth + W_GATE, 294912);   // 1
    rmsnorm_k<<<BT, 256>>>(x, norm_w);                                // 2
    // 3: fused proj+gate GEMM (N=3072)
    gemm_h<5><<<dim3(2*DI/128, BT/128), 256, DSM_BYTES>>>(
        xnh, wth + W_PROJ, nullptr, pgh, DD, 2*DI, nullptr, nullptr, nullptr);
    f2h_k<<<(294912+255)/256, 256>>>(out_proj_w, wth + W_OUTP, 294912); // 4
    // 5: conv + gate (reads fused pg buffer)
    conv_gate_k<<<(unsigned)(((long)BT*DI/4 + 255)/256), 256>>>(conv_w, conv_b);
    f2h_k<<<(147456+255)/256, 256>>>(write_w, wth + W_WRIT, 147456);
    // out projection (fp16 only) + write projection (fp16)
    dim3 g2(DD/128, BT/128);
    gemm_h<5><<<g2, 256, DSM_BYTES>>>(uh, wth + W_OUTP, nullptr, oh, DI, DD, nullptr, nullptr, nullptr);
    gemm_h<5><<<g2, 256, DSM_BYTES>>>(oh, wth + W_WRIT, nullptr, vh, DD, DD, nullptr, nullptr, nullptr);
    // transpose, chunk outer products
    tpose_k<<<dim3(TT/32, DD/32, BB), dim3(32,8)>>>(decay);
    u_batch_h<<<dim3(6,6,BB*(NCH-1)), 256>>>();
    // scan: s_batch hidden under wscan group 1, intra hidden under group 2
    wscan_sbatch_k<<<BB*NCH + WSB, 256>>>(decay);     // s_batch + slots 1-8
    wscan_intra_k<<<6*BB*NCH + WSB, 256>>>(decay);    // intra  + slots 9-16
    wscan_h<<<WSB, 256>>>(17, 8, decay);              // slots 17-24
    wscan_h<<<WSB, 256>>>(25, 6, decay);              // slots 25-30
    // inter reads (fp16 accumulate into readsh)
    gemm_h<2><<<dim3(6,1,BB*(NCH-1)), 256, DSM_BYTES>>>(oh, wbh, nullptr, readsh, DD, DD, nullptr, nullptr, decay);
    // final: out = x + oh + alpha*(readsh @ read_w^T)
    f2h_k<<<(147456+255)/256, 256>>>(read_w, wth + W_READ, 147456);
    gemm_h<7><<<g2, 256, DSM_BYTES>>>(readsh, wth + W_READ, out, oh, DD, DD, x, nullptr, log_alpha);
}

// round 14
// speedup vs baseline: 1.0956x; 1.0956x over previous
#include <cuda_runtime.h>
#include <cuda_fp16.h>
#include <math.h>
#include <stdint.h>

#define BB 8
#define TT 4096
#define DD 768
#define DI 1536
#define BT (BB*TT)
#define CH 128
#define NCH 32
#define EPS 1e-5f
#define WSB 2304                    // wscan blocks (BB*DD*DD/8/256)

// ---------------- scratch (device globals) ----------------------------------
__device__ __half g_xnh[(size_t)BT*DD];
__device__ __half g_pgh[(size_t)BT*2*DI];          // fused proj|gate output [BT,3072]
__device__ __half g_uh[(size_t)BT*DI];
__device__ __half g_oh[(size_t)BT*DD];
__device__ __half g_vh[(size_t)BT*DD];
__device__ __half g_readsh[(size_t)BT*DD];
__device__ __half g_wth[4718592];                  // fp16 weights
__device__ __half g_Wbh[(size_t)(NCH-1)*BB*DD*DD]; // fp16 W slots
__device__ __half g_vTs[(size_t)BB*DD*TT];         // fp16 v^T, gw-scaled
__device__ __half g_kT[(size_t)BB*DD*TT];          // fp16 shifted-keys^T
__device__ __half g_SMh[(size_t)BB*NCH*CH*CH];     // rescaled masked S (fp16)
__device__ float g_out[(size_t)BT*DD];             // conv-mix out (fp32 residual)
__device__ float g_reads[(size_t)BT*DD];           // attention reads (fp32)

#define W_PROJ 0
#define W_GATE 1179648
#define W_OUTP 2359296
#define W_WRIT 3538944
#define W_READ 4128768

// ---------------- small helpers ---------------------------------------------
__device__ __forceinline__ unsigned smem_u32(const void* p){
    return (unsigned)__cvta_generic_to_shared(p);
}
__device__ __forceinline__ void cpa16(unsigned s, const void* g){
    asm volatile("cp.async.cg.shared.global [%0], [%1], 16;" :: "r"(s), "l"(g));
}
__device__ __forceinline__ void mma16(float* c, const unsigned* a, const unsigned* b){
    asm volatile("mma.sync.aligned.m16n8k16.row.col.f32.f16.f16.f32 "
        "{%0,%1,%2,%3}, {%4,%5,%6,%7}, {%8,%9}, {%0,%1,%2,%3};"
        : "+f"(c[0]), "+f"(c[1]), "+f"(c[2]), "+f"(c[3])
        : "r"(a[0]), "r"(a[1]), "r"(a[2]), "r"(a[3]), "r"(b[0]), "r"(b[1]));
}
__device__ __forceinline__ void ldsm4(unsigned& r0, unsigned& r1, unsigned& r2, unsigned& r3,
                                      unsigned addr){
    asm volatile("ldmatrix.sync.aligned.m8n8.x4.shared.b16 {%0,%1,%2,%3}, [%4];"
        : "=r"(r0), "=r"(r1), "=r"(r2), "=r"(r3) : "r"(addr));
}

// ================= 64-wide K-tile, 3-stage, 1-sync GEMM machinery ===========
#define SW 36                       // words per 64-half row (32 + 4 pad)
#define STW (2*128*SW)              // words per stage (A + B)
#define DSM_BYTES (3*STW*4)         // 110592 B

__device__ __forceinline__ void ldh64(unsigned* S, const __half* src, int ldk, int tid){
    unsigned sb = smem_u32(S);
    #pragma unroll
    for (int s = 0; s < 4; s++){
        int q = tid + 256*s; int r = q>>3, c = q&7;
        cpa16(sb + (unsigned)(r*SW + c*4)*4u, src + (size_t)r*ldk + c*8);
    }
}

__device__ __forceinline__ void mma_tile64(unsigned Au, unsigned Bu,
                                           float (&acc)[4][4][4], int lane, int wm, int wn){
    int arow  = wm*64 + (lane & 15);
    int aoffw = (lane >> 4) << 2;
    int bcol0 = wn*32 + ((lane >> 4) << 3) + (lane & 7);
    int boffw = ((lane >> 3) & 1) << 2;
    #pragma unroll
    for (int kk2 = 0; kk2 < 32; kk2 += 8){
        unsigned a[4][4], b[2][4];
        #pragma unroll
        for (int mi = 0; mi < 4; mi++)
            ldsm4(a[mi][0], a[mi][1], a[mi][2], a[mi][3],
                  Au + (unsigned)(((arow + mi*16)*SW + kk2 + aoffw) * 4));
        #pragma unroll
        for (int p = 0; p < 2; p++)
            ldsm4(b[p][0], b[p][1], b[p][2], b[p][3],
                  Bu + (unsigned)(((bcol0 + p*16)*SW + kk2 + boffw) * 4));
        #pragma unroll
        for (int mi = 0; mi < 4; mi++){
            mma16(acc[mi][0], a[mi], &b[0][0]);
            mma16(acc[mi][1], a[mi], &b[0][2]);
            mma16(acc[mi][2], a[mi], &b[1][0]);
            mma16(acc[mi][3], a[mi], &b[1][2]);
        }
    }
}

// EPI: 0 fp32 store; 1 final (base1+base2+alpha*acc); 2 inter (reads += gp*acc,
//      dual store); 5 half store; 6 dual store.  Requires K % 64 == 0, K >= 128.
template<int EPI>
__global__ void __launch_bounds__(256, 2)
gemm_h(const __half* __restrict__ A, const __half* __restrict__ Bw,
       float* __restrict__ C, __half* __restrict__ Ch, int K, int N,
       const float* __restrict__ base1, const float* __restrict__ base2,
       const float* __restrict__ sp)
{
    extern __shared__ unsigned dsm[];
    int tid = threadIdx.x, lane = tid&31, warp = tid>>5;
    int wm = warp>>2, wn = warp&3;
    int bn = blockIdx.x*128;
    size_t bm, aoff, boff, coff;
    if (EPI == 2){
        int z = blockIdx.z, b = z/(NCH-1), n = z%(NCH-1) + 1;
        aoff = ((size_t)b*TT + (size_t)n*CH)*DD;
        boff = ((size_t)(n-1)*BB + b)*(size_t)DD*DD;
        coff = aoff; bm = 0;
    } else { bm = (size_t)blockIdx.y*128; aoff = 0; boff = 0; coff = 0; }

    float acc[4][4][4];
    #pragma unroll
    for (int i=0;i<4;i++)
        #pragma unroll
        for(int j=0;j<4;j++)
            #pragma unroll
            for(int q=0;q<4;q++) acc[i][j][q]=0.f;

    const __half* Ag = A + aoff + bm*(size_t)K;
    const __half* Bg = Bw + boff + (size_t)bn*K;
    int nk = K >> 6;
    unsigned dsmu = smem_u32(dsm);

    ldh64(dsm,            Ag,      K, tid);
    ldh64(dsm + 128*SW,   Bg,      K, tid);
    asm volatile("cp.async.commit_group;" ::: "memory");
    ldh64(dsm + STW,          Ag + 64, K, tid);
    ldh64(dsm + STW + 128*SW, Bg + 64, K, tid);
    asm volatile("cp.async.commit_group;" ::: "memory");

    int cur = 0, nxt = 2;
    for (int t = 0; t < nk; t++){
        asm volatile("cp.async.wait_group 1;" ::: "memory");
        __syncthreads();
        if (t + 2 < nk){
            ldh64(dsm + nxt*STW,          Ag + (t+2)*64, K, tid);
            ldh64(dsm + nxt*STW + 128*SW, Bg + (t+2)*64, K, tid);
        }
        asm volatile("cp.async.commit_group;" ::: "memory");
        mma_tile64(dsmu + (unsigned)(cur*STW*4),
                   dsmu + (unsigned)((cur*STW + 128*SW)*4), acc, lane, wm, wn);
        cur = (cur == 2) ? 0 : cur + 1;
        nxt = (nxt == 2) ? 0 : nxt + 1;
    }

    int tg = lane&3, gid = lane>>2;
    float alpha = (EPI==1) ? expf(sp[0]) : 0.f;
    float lg = 0.f;
    if (EPI==2){
        float gamma = 1.f/(1.f+expf(-sp[0]));
        lg = logf(gamma);
    }
    #pragma unroll
    for (int mi=0;mi<4;mi++){
        float s0 = 0.f, s1 = 0.f;
        if (EPI==2){
            s0 = expf((float)(wm*64 + mi*16 + gid)*lg);
            s1 = expf((float)(wm*64 + mi*16 + gid + 8)*lg);
        }
        #pragma unroll
        for (int ni=0;ni<4;ni++){
            int row = (int)bm + wm*64 + mi*16 + gid;
            int col = bn + wn*32 + ni*8 + 2*tg;
            size_t i0 = coff + (size_t)row*N + col;
            size_t i1 = coff + (size_t)(row+8)*N + col;
            float a0 = acc[mi][ni][0], a1 = acc[mi][ni][1];
            float a2 = acc[mi][ni][2], a3 = acc[mi][ni][3];
            if (EPI == 0){
                *(float2*)(C+i0) = make_float2(a0, a1);
                *(float2*)(C+i1) = make_float2(a2, a3);
            } else if (EPI == 5){
                *(__half2*)(Ch+i0) = __floats2half2_rn(a0, a1);
                *(__half2*)(Ch+i1) = __floats2half2_rn(a2, a3);
            } else if (EPI == 6){
                *(float2*)(C+i0) = make_float2(a0, a1);
                *(float2*)(C+i1) = make_float2(a2, a3);
                *(__half2*)(Ch+i0) = __floats2half2_rn(a0, a1);
                *(__half2*)(Ch+i1) = __floats2half2_rn(a2, a3);
            } else if (EPI == 2){
                float2 c0 = *(const float2*)(C+i0);
                float2 c1 = *(const float2*)(C+i1);
                c0.x += s0*a0; c0.y += s0*a1;
                c1.x += s1*a2; c1.y += s1*a3;
                *(float2*)(C+i0) = c0;
                *(float2*)(C+i1) = c1;
                *(__half2*)(Ch+i0) = __floats2half2_rn(c0.x, c0.y);
                *(__half2*)(Ch+i1) = __floats2half2_rn(c1.x, c1.y);
            } else { // EPI==1
                float2 x0 = *(const float2*)(base1+i0), o0 = *(const float2*)(base2+i0);
                float2 x1 = *(const float2*)(base1+i1), o1 = *(const float2*)(base2+i1);
                *(float2*)(C+i0) = make_float2(x0.x+o0.x+alpha*a0, x0.y+o0.y+alpha*a1);
                *(float2*)(C+i1) = make_float2(x1.x+o1.x+alpha*a2, x1.y+o1.y+alpha*a3);
            }
        }
    }
}

// ================= 32-wide K-tile 2-stage machinery (scan kernels) ==========
#define SMH 20

__device__ __forceinline__ void ldh(unsigned* S, const __half* src, int ldk, int tid){
    unsigned sb = smem_u32(S);
    #pragma unroll
    for (int s = 0; s < 2; s++){
        int q = tid + 256*s; int r = q>>2, kc8 = (q&3)<<3;
        cpa16(sb + (unsigned)(r*SMH + (kc8>>1))*4u, src + (size_t)r*ldk + kc8);
    }
}

__device__ __forceinline__ void mma_tile_h(unsigned Au, unsigned Bu,
                                           float (&acc)[4][4][4], int lane, int wm, int wn){
    int arow  = wm*64 + (lane & 15);
    int aoffw = (lane >> 4) << 2;
    int bcol0 = wn*32 + ((lane >> 4) << 3) + (lane & 7);
    int boffw = ((lane >> 3) & 1) << 2;
    #pragma unroll
    for (int kk2 = 0; kk2 < 16; kk2 += 8){
        unsigned a[4][4], b[2][4];
        #pragma unroll
        for (int mi = 0; mi < 4; mi++)
            ldsm4(a[mi][0], a[mi][1], a[mi][2], a[mi][3],
                  Au + (unsigned)(((arow + mi*16)*SMH + kk2 + aoffw) * 4));
        #pragma unroll
        for (int p = 0; p < 2; p++)
            ldsm4(b[p][0], b[p][1], b[p][2], b[p][3],
                  Bu + (unsigned)(((bcol0 + p*16)*SMH + kk2 + boffw) * 4));
        #pragma unroll
        for (int mi = 0; mi < 4; mi++){
            mma16(acc[mi][0], a[mi], &b[0][0]);
            mma16(acc[mi][1], a[mi], &b[0][2]);
            mma16(acc[mi][2], a[mi], &b[1][0]);
            mma16(acc[mi][3], a[mi], &b[1][2]);
        }
    }
}

// ---------------- wscan body: grouped serial AXPY over fp16 slots -----------
__device__ void wscan_body(int bid, int tid, int s0, int cnt, const float* decay_p){
    const size_t n = (size_t)BB*DD*DD;
    size_t i = ((size_t)bid*256 + tid)*8;
    if (i >= n) return;
    float gamma = 1.f/(1.f+expf(-decay_p[0]));
    float gC = expf(128.f*logf(gamma));
    uint4 pv = *(const uint4*)(g_Wbh + (size_t)(s0-1)*n + i);
    float2 p[4];
    p[0] = __half22float2(*(__half2*)&pv.x);
    p[1] = __half22float2(*(__half2*)&pv.y);
    p[2] = __half22float2(*(__half2*)&pv.z);
    p[3] = __half22float2(*(__half2*)&pv.w);
    for (int j = 0; j < cnt; j++){
        uint4* cur = (uint4*)(g_Wbh + (size_t)(s0+j)*n + i);
        uint4 cv = *cur;
        float2 c[4];
        c[0] = __half22float2(*(__half2*)&cv.x);
        c[1] = __half22float2(*(__half2*)&cv.y);
        c[2] = __half22float2(*(__half2*)&cv.z);
        c[3] = __half22float2(*(__half2*)&cv.w);
        #pragma unroll
        for (int q = 0; q < 4; q++){ c[q].x += gC*p[q].x; c[q].y += gC*p[q].y; p[q] = c[q]; }
        *(__half2*)&cv.x = __floats2half2_rn(c[0].x, c[0].y);
        *(__half2*)&cv.y = __floats2half2_rn(c[1].x, c[1].y);
        *(__half2*)&cv.z = __floats2half2_rn(c[2].x, c[2].y);
        *(__half2*)&cv.w = __floats2half2_rn(c[3].x, c[3].y);
        *cur = cv;
    }
}

// ---------------- s_batch body: masked rescaled S (fp16) --------------------
__device__ void s_batch_body(unsigned* As0, unsigned* Bs0, int z, int tid,
                             const float* decay_p){
    int b = z/NCH, n = z%NCH;
    int lane = tid&31, warp = tid>>5, wm = warp>>2, wn = warp&3;
    float acc[4][4][4];
    #pragma unroll
    for (int i=0;i<4;i++)
        #pragma unroll
        for(int j=0;j<4;j++)
            #pragma unroll
            for(int q=0;q<4;q++) acc[i][j][q]=0.f;

    const __half* rb = g_oh + ((size_t)b*TT + (size_t)n*CH)*DD;
    const __half* kb = rb - DD;
    bool z0 = (n == 0);

    auto ldb = [&](unsigned* S, int k0){
        unsigned sb = smem_u32(S);
        #pragma unroll
        for (int s = 0; s < 2; s++){
            int q = tid + 256*s; int r = q>>2, kc8 = (q&3)<<3;
            if (z0 && r == 0){
                *(uint4*)(S + r*SMH + (kc8>>1)) = make_uint4(0,0,0,0);
            } else {
                cpa16(sb + (unsigned)(r*SMH + (kc8>>1))*4u, kb + (size_t)r*DD + k0 + kc8);
            }
        }
    };

    ldh(As0, rb, DD, tid);
    ldb(Bs0, 0);
    asm volatile("cp.async.commit_group;" ::: "memory");
    int nk = DD >> 5;
    for (int t = 0; t < nk; t++){
        int cur = t & 1;
        if (t + 1 < nk){
            ldh(As0 + (cur^1)*128*SMH, rb + (t+1)*32, DD, tid);
            ldb(Bs0 + (cur^1)*128*SMH, (t+1)*32);
            asm volatile("cp.async.commit_group;" ::: "memory");
            asm volatile("cp.async.wait_group 1;" ::: "memory");
        } else {
            asm volatile("cp.async.wait_group 0;" ::: "memory");
        }
        __syncthreads();
        mma_tile_h(smem_u32(As0 + cur*128*SMH), smem_u32(Bs0 + cur*128*SMH),
                   acc, lane, wm, wn);
        __syncthreads();
    }

    float gamma = 1.f/(1.f+expf(-decay_p[0]));
    float lg = logf(gamma);
    __half* smb = g_SMh + ((size_t)b*NCH + n)*CH*CH;
    int tg=lane&3, gid=lane>>2;
    #pragma unroll
    for (int mi=0;mi<4;mi++){
        int c0r = wm*64 + mi*16 + gid;
        float sc0 = expf((float)(c0r - 128)*lg);
        float sc1 = expf((float)(c0r - 120)*lg);
        #pragma unroll
        for (int ni=0;ni<4;ni++){
            int e0c = wn*32 + ni*8 + 2*tg;
            float v0 = (c0r   > e0c  ) ? sc0*acc[mi][ni][0] : 0.f;
            float v1 = (c0r   > e0c+1) ? sc0*acc[mi][ni][1] : 0.f;
            float v2 = (c0r+8 > e0c  ) ? sc1*acc[mi][ni][2] : 0.f;
            float v3 = (c0r+8 > e0c+1) ? sc1*acc[mi][ni][3] : 0.f;
            *(__half2*)(smb + (size_t)c0r*CH + e0c)     = __floats2half2_rn(v0, v1);
            *(__half2*)(smb + (size_t)(c0r+8)*CH + e0c) = __floats2half2_rn(v2, v3);
        }
    }
}

// ---------------- intra body: reads = SM' @ vTs^T (fp16, dual store) --------
__device__ void intra_body(unsigned* As0, unsigned* Bs0, int z, int bn, int tid){
    int b = z/NCH, n = z%NCH;
    int lane = tid&31, warp = tid>>5, wm = warp>>2, wn = warp&3;
    float acc[4][4][4];
    #pragma unroll
    for (int i=0;i<4;i++)
        #pragma unroll
        for(int j=0;j<4;j++)
            #pragma unroll
            for(int q=0;q<4;q++) acc[i][j][q]=0.f;

    const __half* Ag = g_SMh + ((size_t)b*NCH + n)*CH*CH;
    const __half* Bg = g_vTs + ((size_t)b*DD + bn)*TT + (size_t)n*CH;

    ldh(As0, Ag, CH, tid);
    ldh(Bs0, Bg, TT, tid);
    asm volatile("cp.async.commit_group;" ::: "memory");
    const int nk = CH >> 5;   // 4
    for (int t = 0; t < nk; t++){
        int cur = t & 1;
        if (t + 1 < nk){
            ldh(As0 + (cur^1)*128*SMH, Ag + (t+1)*32, CH, tid);
            ldh(Bs0 + (cur^1)*128*SMH, Bg + (t+1)*32, TT, tid);
            asm volatile("cp.async.commit_group;" ::: "memory");
            asm volatile("cp.async.wait_group 1;" ::: "memory");
        } else {
            asm volatile("cp.async.wait_group 0;" ::: "memory");
        }
        __syncthreads();
        mma_tile_h(smem_u32(As0 + cur*128*SMH), smem_u32(Bs0 + cur*128*SMH),
                   acc, lane, wm, wn);
        __syncthreads();
    }

    size_t ob = ((size_t)b*TT + (size_t)n*CH)*DD + bn;
    int tg=lane&3, gid=lane>>2;
    #pragma unroll
    for (int mi=0;mi<4;mi++){
        #pragma unroll
        for (int ni=0;ni<4;ni++){
            int row = wm*64 + mi*16 + gid;
            int col = wn*32 + ni*8 + 2*tg;
            size_t i0 = ob + (size_t)row*DD + col;
            size_t i1 = ob + (size_t)(row+8)*DD + col;
            *(float2*)(g_reads+i0) = make_float2(acc[mi][ni][0], acc[mi][ni][1]);
            *(float2*)(g_reads+i1) = make_float2(acc[mi][ni][2], acc[mi][ni][3]);
            *(__half2*)(g_readsh+i0) = __floats2half2_rn(acc[mi][ni][0], acc[mi][ni][1]);
            *(__half2*)(g_readsh+i1) = __floats2half2_rn(acc[mi][ni][2], acc[mi][ni][3]);
        }
    }
}

// ---------------- combined launches: scan GEMMs hidden under wscan ----------
__global__ void __launch_bounds__(256)
wscan_sbatch_k(const float* __restrict__ decay_p){
    __shared__ unsigned As[2*128*SMH], Bs[2*128*SMH];
    int tid = threadIdx.x;
    if ((int)blockIdx.x < BB*NCH)
        s_batch_body(As, Bs, blockIdx.x, tid, decay_p);
    else
        wscan_body(blockIdx.x - BB*NCH, tid, 1, 8, decay_p);
}
__global__ void __launch_bounds__(256)
wscan_intra_k(const float* __restrict__ decay_p){
    __shared__ unsigned As[2*128*SMH], Bs[2*128*SMH];
    int tid = threadIdx.x;
    if ((int)blockIdx.x < 6*BB*NCH){
        int q = blockIdx.x;
        intra_body(As, Bs, q/6, (q%6)*128, tid);
    } else {
        wscan_body(blockIdx.x - 6*BB*NCH, tid, 9, 8, decay_p);
    }
}
__global__ void wscan_h(int s0, int cnt, const float* __restrict__ decay_p){
    wscan_body(blockIdx.x, threadIdx.x, s0, cnt, decay_p);
}

// ---------------- u_batch (standalone, fp16 GEMM) ---------------------------
__global__ void __launch_bounds__(256)
u_batch_h(){
    __shared__ unsigned As[2][128*SMH], Bs[2][128*SMH];
    int z = blockIdx.z, b = z/(NCH-1), mch = z%(NCH-1);
    int bm = blockIdx.y*128, bn = blockIdx.x*128;
    int tid = threadIdx.x, lane = tid&31, warp = tid>>5;
    int wm = warp>>2, wn = warp&3;
    float acc[4][4][4];
    #pragma unroll
    for (int i=0;i<4;i++)
        #pragma unroll
        for(int j=0;j<4;j++)
            #pragma unroll
            for(int q=0;q<4;q++) acc[i][j][q]=0.f;

    const __half* Ag = g_vTs + ((size_t)b*DD + bm)*TT + (size_t)mch*CH;
    const __half* Bg = g_kT  + ((size_t)b*DD + bn)*TT + (size_t)mch*CH;

    ldh(As[0], Ag, TT, tid);
    ldh(Bs[0], Bg, TT, tid);
    asm volatile("cp.async.commit_group;" ::: "memory");
    const int nk = CH >> 5;
    for (int t = 0; t < nk; t++){
        int cur = t & 1;
        if (t + 1 < nk){
            ldh(As[cur^1], Ag + (t+1)*32, TT, tid);
            ldh(Bs[cur^1], Bg + (t+1)*32, TT, tid);
            asm volatile("cp.async.commit_group;" ::: "memory");
            asm volatile("cp.async.wait_group 1;" ::: "memory");
        } else {
            asm volatile("cp.async.wait_group 0;" ::: "memory");
        }
        __syncthreads();
        mma_tile_h(smem_u32(As[cur]), smem_u32(Bs[cur]), acc, lane, wm, wn);
        __syncthreads();
    }

    __half* Wout = g_Wbh + ((size_t)mch*BB + b)*(size_t)DD*DD;
    int tg = lane&3, gid = lane>>2;
    #pragma unroll
    for (int mi=0;mi<4;mi++){
        #pragma unroll
        for (int ni=0;ni<4;ni++){
            int row = bm + wm*64 + mi*16 + gid;
            int col = bn + wn*32 + ni*8 + 2*tg;
            *(__half2*)(Wout + (size_t)row*DD + col)     = __floats2half2_rn(acc[mi][ni][0], acc[mi][ni][1]);
            *(__half2*)(Wout + (size_t)(row+8)*DD + col) = __floats2half2_rn(acc[mi][ni][2], acc[mi][ni][3]);
        }
    }
}

// ---------------- transpose: build vT (gw-scaled) and shifted-keys^T --------
__global__ void tpose_k(const float* __restrict__ decay_p){
    __shared__ float s1[32][33], s2[32][33];
    int b = blockIdx.z, d0 = blockIdx.y*32, t0 = blockIdx.x*32;
    int tx = threadIdx.x, ty = threadIdx.y;      // 32 x 8
    float gamma = 1.f/(1.f+expf(-decay_p[0]));
    float lg = logf(gamma);
    const __half* vb = g_vh + (size_t)b*TT*DD;
    const __half* ob = g_oh + (size_t)b*TT*DD;
    #pragma unroll
    for (int i = 0; i < 4; i++){
        int tl = ty + 8*i;
        int t = t0 + tl;
        float gw = expf((float)(CH-1-(t&(CH-1)))*lg);
        s1[tl][tx] = __half2float(vb[(size_t)t*DD + d0 + tx]) * gw;
        s2[tl][tx] = (t == 0) ? 0.f : __half2float(ob[(size_t)(t-1)*DD + d0 + tx]);
    }
    __syncthreads();
    __half* vT = g_vTs + (size_t)b*DD*TT;
    __half* kT = g_kT  + (size_t)b*DD*TT;
    #pragma unroll
    for (int i = 0; i < 4; i++){
        int dl = ty + 8*i;
        vT[(size_t)(d0+dl)*TT + t0 + tx] = __float2half_rn(s1[tx][dl]);
        kT[(size_t)(d0+dl)*TT + t0 + tx] = __float2half_rn(s2[tx][dl]);
    }
}

// ---------------- rmsnorm (half out) ----------------------------------------
__global__ void rmsnorm_k(const float* __restrict__ x, const float* __restrict__ w) {
    int row = blockIdx.x;
    const float* xr = x + (size_t)row*DD;
    __half* o = g_xnh + (size_t)row*DD;
    float s = 0.f;
    for (int d = threadIdx.x; d < DD; d += blockDim.x) { float v = xr[d]; s += v*v; }
    __shared__ float red[32];
    for (int off = 16; off; off >>= 1) s += __shfl_down_sync(0xffffffffu, s, off);
    if ((threadIdx.x & 31) == 0) red[threadIdx.x >> 5] = s;
    __syncthreads();
    if (threadIdx.x < 32) {
        float t = (threadIdx.x < (blockDim.x >> 5)) ? red[threadIdx.x] : 0.f;
        for (int off = 16; off; off >>= 1) t += __shfl_down_sync(0xffffffffu, t, off);
        if (threadIdx.x == 0) red[0] = t;
    }
    __syncthreads();
    float scale = rsqrtf(red[0] / (float)DD + EPS);
    for (int d = threadIdx.x; d < DD; d += blockDim.x)
        o[d] = __float2half_rn(xr[d] * scale * w[d]);
}

// ---------------- single-launch weight convert (all 5 weights -> g_wth) -----
// segments (in float4 units): proj 294912 | gate 294912 | outp 294912 |
//                             writ 147456 | read 147456   (total 1179648)
__global__ void prep_k(const float* __restrict__ w0, const float* __restrict__ w1,
                       const float* __restrict__ w2, const float* __restrict__ w3,
                       const float* __restrict__ w4){
    long i = (long)blockIdx.x*256 + threadIdx.x;
    if (i >= 1179648) return;
    const float* src;
    long loc = i;
    if (i < 294912){ src = w0; }
    else if (i < 589824){ src = w1; loc = i - 294912; }
    else if (i < 884736){ src = w2; loc = i - 589824; }
    else if (i < 1032192){ src = w3; loc = i - 884736; }
    else { src = w4; loc = i - 1032192; }
    float4 v = ((const float4*)src)[loc];
    ((__half2*)g_wth)[2*i]   = __floats2half2_rn(v.x, v.y);
    ((__half2*)g_wth)[2*i+1] = __floats2half2_rn(v.z, v.w);
}

// ---------------- depthwise causal conv + silu gate (fused pg buffer) -------
__global__ void conv_gate_k(const float* __restrict__ cw, const float* __restrict__ cb) {
    long j4 = (long)blockIdx.x*blockDim.x + threadIdx.x;
    const long NV = (long)BT*DI/4;
    if (j4 >= NV) return;
    int e4 = (int)(j4 % (DI/4));
    long bl = j4 / (DI/4);
    int l = (int)(bl % TT);
    int e = e4*4;
    float4 acc = *(const float4*)(cb + e);
    #pragma unroll
    for (int jj = 0; jj < 4; jj++){
        int ll = l - 3 + jj;
        if (ll >= 0){
            const __half2* vp = (const __half2*)(g_pgh + (bl-(3-jj))*(2*DI) + e);
            float2 v01 = __half22float2(vp[0]);
            float2 v23 = __half22float2(vp[1]);
            acc.x += v01.x * cw[(e+0)*4+jj];
            acc.y += v01.y * cw[(e+1)*4+jj];
            acc.z += v23.x * cw[(e+2)*4+jj];
            acc.w += v23.y * cw[(e+3)*4+jj];
        }
    }
    const __half2* gp = (const __half2*)(g_pgh + bl*(2*DI) + DI + e);
    float2 g01 = __half22float2(gp[0]);
    float2 g23 = __half22float2(gp[1]);
    float rx = (acc.x/(1.f+expf(-acc.x))) * (g01.x/(1.f+expf(-g01.x)));
    float ry = (acc.y/(1.f+expf(-acc.y))) * (g01.y/(1.f+expf(-g01.y)));
    float rz = (acc.z/(1.f+expf(-acc.z))) * (g23.x/(1.f+expf(-g23.x)));
    float rw = (acc.w/(1.f+expf(-acc.w))) * (g23.y/(1.f+expf(-g23.y)));
    __half2* up = (__half2*)(g_uh + j4*4);
    up[0] = __floats2half2_rn(rx, ry);
    up[1] = __floats2half2_rn(rz, rw);
}

// ---------------- launch ----------------------------------------------------
extern "C" void kernel_launch(void* const* d_in, const int* in_sizes, int n_in,
                              void* d_out, int out_size) {
    const float* x          = (const float*)d_in[0];
    const float* norm_w     = (const float*)d_in[1];
    const float* proj_w     = (const float*)d_in[2];
    const float* gate_w     = (const float*)d_in[3];
    const float* conv_w     = (const float*)d_in[4];
    const float* conv_b     = (const float*)d_in[5];
    const float* out_proj_w = (const float*)d_in[6];
    const float* write_w    = (const float*)d_in[7];
    const float* read_w     = (const float*)d_in[8];
    const float* decay      = (const float*)d_in[9];
    const float* log_alpha  = (const float*)d_in[10];
    float* out = (float*)d_out;

    __half *xnh, *pgh, *uh, *oh, *vh, *readsh, *wth, *wbh;
    float *o, *reads;
    cudaGetSymbolAddress((void**)&xnh,    g_xnh);
    cudaGetSymbolAddress((void**)&pgh,    g_pgh);
    cudaGetSymbolAddress((void**)&uh,     g_uh);
    cudaGetSymbolAddress((void**)&oh,     g_oh);
    cudaGetSymbolAddress((void**)&vh,     g_vh);
    cudaGetSymbolAddress((void**)&readsh, g_readsh);
    cudaGetSymbolAddress((void**)&wth,    g_wth);
    cudaGetSymbolAddress((void**)&wbh,    g_Wbh);
    cudaGetSymbolAddress((void**)&o,      g_out);
    cudaGetSymbolAddress((void**)&reads,  g_reads);

    cudaFuncSetAttribute(gemm_h<1>, cudaFuncAttributeMaxDynamicSharedMemorySize, DSM_BYTES);
    cudaFuncSetAttribute(gemm_h<2>, cudaFuncAttributeMaxDynamicSharedMemorySize, DSM_BYTES);
    cudaFuncSetAttribute(gemm_h<5>, cudaFuncAttributeMaxDynamicSharedMemorySize, DSM_BYTES);
    cudaFuncSetAttribute(gemm_h<6>, cudaFuncAttributeMaxDynamicSharedMemorySize, DSM_BYTES);

    // 0: all weight converts in one launch; 1: rmsnorm
    prep_k<<<(1179648+255)/256, 256>>>(proj_w, gate_w, out_proj_w, write_w, read_w);
    rmsnorm_k<<<BT, 256>>>(x, norm_w);
    // 2: fused proj+gate GEMM (N=3072, weights adjacent in g_wth)
    gemm_h<5><<<dim3(2*DI/128, BT/128), 256, DSM_BYTES>>>(
        xnh, wth + W_PROJ, nullptr, pgh, DD, 2*DI, nullptr, nullptr, nullptr);
    // 3: conv + gate (reads fused pg buffer)  -> profiled launch
    conv_gate_k<<<(unsigned)(((long)BT*DI/4 + 255)/256), 256>>>(conv_w, conv_b);
    // out projection (dual store) + write projection (fp16)
    dim3 g2(DD/128, BT/128);
    gemm_h<6><<<g2, 256, DSM_BYTES>>>(uh, wth + W_OUTP, o, oh, DI, DD, nullptr, nullptr, nullptr);
    gemm_h<5><<<g2, 256, DSM_BYTES>>>(oh, wth + W_WRIT, nullptr, vh, DD, DD, nullptr, nullptr, nullptr);
    // transpose, chunk outer products
    tpose_k<<<dim3(TT/32, DD/32, BB), dim3(32,8)>>>(decay);
    u_batch_h<<<dim3(6,6,BB*(NCH-1)), 256>>>();
    // scan: s_batch hidden under wscan group 1, intra hidden under group 2
    wscan_sbatch_k<<<BB*NCH + WSB, 256>>>(decay);     // s_batch + slots 1-8
    wscan_intra_k<<<6*BB*NCH + WSB, 256>>>(decay);    // intra  + slots 9-16
    wscan_h<<<WSB, 256>>>(17, 8, decay);              // slots 17-24
    wscan_h<<<WSB, 256>>>(25, 6, decay);              // slots 25-30
    // inter reads (fp16, accumulate into reads)
    gemm_h<2><<<dim3(6,1,BB*(NCH-1)), 256, DSM_BYTES>>>(oh, wbh, reads, readsh, DD, DD, nullptr, nullptr, decay);
    // final: out = x + o + alpha*(reads @ read_w^T)
    gemm_h<1><<<g2, 256, DSM_BYTES>>>(readsh, wth + W_READ, out, nullptr, DD, DD, x, o, log_alpha);
}

// round 15
// speedup vs baseline: 1.2097x; 1.1041x over previous
#include <cuda_runtime.h>
#include <cuda_fp16.h>
#include <math.h>
#include <stdint.h>

#define BB 8
#define TT 4096
#define DD 768
#define DI 1536
#define BT (BB*TT)
#define CH 128
#define NCH 32
#define EPS 1e-5f
#define WSB 2304                    // wscan blocks (BB*DD*DD/8/256)

// ---------------- scratch (device globals) ----------------------------------
__device__ __half g_xnh[(size_t)BT*DD];
__device__ __half g_pgh[(size_t)BT*2*DI];          // fused proj|gate output [BT,3072]
__device__ __half g_uh[(size_t)BT*DI];
__device__ __half g_oh[(size_t)BT*DD];
__device__ __half g_vh[(size_t)BT*DD];
__device__ __half g_readsh[(size_t)BT*DD];
__device__ __half g_wth[4718592];                  // fp16 weights
__device__ __half g_Wbh[(size_t)(NCH-1)*BB*DD*DD]; // fp16 W slots
__device__ __half g_vTs[(size_t)BB*DD*TT];         // fp16 v^T, gw-scaled
__device__ __half g_kT[(size_t)BB*DD*TT];          // fp16 shifted-keys^T
__device__ __half g_SMh[(size_t)BB*NCH*CH*CH];     // rescaled masked S (fp16)
__device__ float g_out[(size_t)BT*DD];             // conv-mix out (fp32 residual)
__device__ float g_reads[(size_t)BT*DD];           // attention reads (fp32)

#define W_PROJ 0
#define W_GATE 1179648
#define W_OUTP 2359296
#define W_WRIT 3538944
#define W_READ 4128768

// ---------------- small helpers ---------------------------------------------
__device__ __forceinline__ unsigned smem_u32(const void* p){
    return (unsigned)__cvta_generic_to_shared(p);
}
__device__ __forceinline__ void cpa16(unsigned s, const void* g){
    asm volatile("cp.async.cg.shared.global [%0], [%1], 16;" :: "r"(s), "l"(g));
}
__device__ __forceinline__ void mma16(float* c, const unsigned* a, const unsigned* b){
    asm volatile("mma.sync.aligned.m16n8k16.row.col.f32.f16.f16.f32 "
        "{%0,%1,%2,%3}, {%4,%5,%6,%7}, {%8,%9}, {%0,%1,%2,%3};"
        : "+f"(c[0]), "+f"(c[1]), "+f"(c[2]), "+f"(c[3])
        : "r"(a[0]), "r"(a[1]), "r"(a[2]), "r"(a[3]), "r"(b[0]), "r"(b[1]));
}
__device__ __forceinline__ void ldsm4(unsigned& r0, unsigned& r1, unsigned& r2, unsigned& r3,
                                      unsigned addr){
    asm volatile("ldmatrix.sync.aligned.m8n8.x4.shared.b16 {%0,%1,%2,%3}, [%4];"
        : "=r"(r0), "=r"(r1), "=r"(r2), "=r"(r3) : "r"(addr));
}

// ================= 64-wide K-tile, 3-stage, 1-sync GEMM machinery ===========
#define SW 36                       // words per 64-half row (32 + 4 pad)
#define STW (2*128*SW)              // words per stage (A + B)
#define DSM_BYTES (3*STW*4)         // 110592 B

__device__ __forceinline__ void ldh64(unsigned* S, const __half* src, int ldk, int tid){
    unsigned sb = smem_u32(S);
    #pragma unroll
    for (int s = 0; s < 4; s++){
        int q = tid + 256*s; int r = q>>3, c = q&7;
        cpa16(sb + (unsigned)(r*SW + c*4)*4u, src + (size_t)r*ldk + c*8);
    }
}

__device__ __forceinline__ void mma_tile64(unsigned Au, unsigned Bu,
                                           float (&acc)[4][4][4], int lane, int wm, int wn){
    int arow  = wm*64 + (lane & 15);
    int aoffw = (lane >> 4) << 2;
    int bcol0 = wn*32 + ((lane >> 4) << 3) + (lane & 7);
    int boffw = ((lane >> 3) & 1) << 2;
    #pragma unroll
    for (int kk2 = 0; kk2 < 32; kk2 += 8){
        unsigned a[4][4], b[2][4];
        #pragma unroll
        for (int mi = 0; mi < 4; mi++)
            ldsm4(a[mi][0], a[mi][1], a[mi][2], a[mi][3],
                  Au + (unsigned)(((arow + mi*16)*SW + kk2 + aoffw) * 4));
        #pragma unroll
        for (int p = 0; p < 2; p++)
            ldsm4(b[p][0], b[p][1], b[p][2], b[p][3],
                  Bu + (unsigned)(((bcol0 + p*16)*SW + kk2 + boffw) * 4));
        #pragma unroll
        for (int mi = 0; mi < 4; mi++){
            mma16(acc[mi][0], a[mi], &b[0][0]);
            mma16(acc[mi][1], a[mi], &b[0][2]);
            mma16(acc[mi][2], a[mi], &b[1][0]);
            mma16(acc[mi][3], a[mi], &b[1][2]);
        }
    }
}

// EPI: 0 fp32 store; 1 final (base1+base2+alpha*acc); 2 inter (reads += gp*acc,
//      dual store); 5 half store; 6 dual store.  Requires K % 64 == 0, K >= 128.
template<int EPI>
__global__ void __launch_bounds__(256, 2)
gemm_h(const __half* __restrict__ A, const __half* __restrict__ Bw,
       float* __restrict__ C, __half* __restrict__ Ch, int K, int N,
       const float* __restrict__ base1, const float* __restrict__ base2,
       const float* __restrict__ sp)
{
    extern __shared__ unsigned dsm[];
    int tid = threadIdx.x, lane = tid&31, warp = tid>>5;
    int wm = warp>>2, wn = warp&3;
    int bn = blockIdx.x*128;
    size_t bm, aoff, boff, coff;
    if (EPI == 2){
        int z = blockIdx.z, b = z/(NCH-1), n = z%(NCH-1) + 1;
        aoff = ((size_t)b*TT + (size_t)n*CH)*DD;
        boff = ((size_t)(n-1)*BB + b)*(size_t)DD*DD;
        coff = aoff; bm = 0;
    } else { bm = (size_t)blockIdx.y*128; aoff = 0; boff = 0; coff = 0; }

    float acc[4][4][4];
    #pragma unroll
    for (int i=0;i<4;i++)
        #pragma unroll
        for(int j=0;j<4;j++)
            #pragma unroll
            for(int q=0;q<4;q++) acc[i][j][q]=0.f;

    const __half* Ag = A + aoff + bm*(size_t)K;
    const __half* Bg = Bw + boff + (size_t)bn*K;
    int nk = K >> 6;
    unsigned dsmu = smem_u32(dsm);

    ldh64(dsm,            Ag,      K, tid);
    ldh64(dsm + 128*SW,   Bg,      K, tid);
    asm volatile("cp.async.commit_group;" ::: "memory");
    ldh64(dsm + STW,          Ag + 64, K, tid);
    ldh64(dsm + STW + 128*SW, Bg + 64, K, tid);
    asm volatile("cp.async.commit_group;" ::: "memory");

    int cur = 0, nxt = 2;
    for (int t = 0; t < nk; t++){
        asm volatile("cp.async.wait_group 1;" ::: "memory");
        __syncthreads();
        if (t + 2 < nk){
            ldh64(dsm + nxt*STW,          Ag + (t+2)*64, K, tid);
            ldh64(dsm + nxt*STW + 128*SW, Bg + (t+2)*64, K, tid);
        }
        asm volatile("cp.async.commit_group;" ::: "memory");
        mma_tile64(dsmu + (unsigned)(cur*STW*4),
                   dsmu + (unsigned)((cur*STW + 128*SW)*4), acc, lane, wm, wn);
        cur = (cur == 2) ? 0 : cur + 1;
        nxt = (nxt == 2) ? 0 : nxt + 1;
    }

    int tg = lane&3, gid = lane>>2;
    float alpha = (EPI==1) ? expf(sp[0]) : 0.f;
    float lg = 0.f;
    if (EPI==2){
        float gamma = 1.f/(1.f+expf(-sp[0]));
        lg = logf(gamma);
    }
    #pragma unroll
    for (int mi=0;mi<4;mi++){
        float s0 = 0.f, s1 = 0.f;
        if (EPI==2){
            s0 = expf((float)(wm*64 + mi*16 + gid)*lg);
            s1 = expf((float)(wm*64 + mi*16 + gid + 8)*lg);
        }
        #pragma unroll
        for (int ni=0;ni<4;ni++){
            int row = (int)bm + wm*64 + mi*16 + gid;
            int col = bn + wn*32 + ni*8 + 2*tg;
            size_t i0 = coff + (size_t)row*N + col;
            size_t i1 = coff + (size_t)(row+8)*N + col;
            float a0 = acc[mi][ni][0], a1 = acc[mi][ni][1];
            float a2 = acc[mi][ni][2], a3 = acc[mi][ni][3];
            if (EPI == 0){
                *(float2*)(C+i0) = make_float2(a0, a1);
                *(float2*)(C+i1) = make_float2(a2, a3);
            } else if (EPI == 5){
                *(__half2*)(Ch+i0) = __floats2half2_rn(a0, a1);
                *(__half2*)(Ch+i1) = __floats2half2_rn(a2, a3);
            } else if (EPI == 6){
                *(float2*)(C+i0) = make_float2(a0, a1);
                *(float2*)(C+i1) = make_float2(a2, a3);
                *(__half2*)(Ch+i0) = __floats2half2_rn(a0, a1);
                *(__half2*)(Ch+i1) = __floats2half2_rn(a2, a3);
            } else if (EPI == 2){
                float2 c0 = *(const float2*)(C+i0);
                float2 c1 = *(const float2*)(C+i1);
                c0.x += s0*a0; c0.y += s0*a1;
                c1.x += s1*a2; c1.y += s1*a3;
                *(float2*)(C+i0) = c0;
                *(float2*)(C+i1) = c1;
                *(__half2*)(Ch+i0) = __floats2half2_rn(c0.x, c0.y);
                *(__half2*)(Ch+i1) = __floats2half2_rn(c1.x, c1.y);
            } else { // EPI==1
                float2 x0 = *(const float2*)(base1+i0), o0 = *(const float2*)(base2+i0);
                float2 x1 = *(const float2*)(base1+i1), o1 = *(const float2*)(base2+i1);
                *(float2*)(C+i0) = make_float2(x0.x+o0.x+alpha*a0, x0.y+o0.y+alpha*a1);
                *(float2*)(C+i1) = make_float2(x1.x+o1.x+alpha*a2, x1.y+o1.y+alpha*a3);
            }
        }
    }
}

// ================= 32-wide K-tile 2-stage machinery (scan kernels) ==========
#define SMH 20

__device__ __forceinline__ void ldh(unsigned* S, const __half* src, int ldk, int tid){
    unsigned sb = smem_u32(S);
    #pragma unroll
    for (int s = 0; s < 2; s++){
        int q = tid + 256*s; int r = q>>2, kc8 = (q&3)<<3;
        cpa16(sb + (unsigned)(r*SMH + (kc8>>1))*4u, src + (size_t)r*ldk + kc8);
    }
}

__device__ __forceinline__ void mma_tile_h(unsigned Au, unsigned Bu,
                                           float (&acc)[4][4][4], int lane, int wm, int wn){
    int arow  = wm*64 + (lane & 15);
    int aoffw = (lane >> 4) << 2;
    int bcol0 = wn*32 + ((lane >> 4) << 3) + (lane & 7);
    int boffw = ((lane >> 3) & 1) << 2;
    #pragma unroll
    for (int kk2 = 0; kk2 < 16; kk2 += 8){
        unsigned a[4][4], b[2][4];
        #pragma unroll
        for (int mi = 0; mi < 4; mi++)
            ldsm4(a[mi][0], a[mi][1], a[mi][2], a[mi][3],
                  Au + (unsigned)(((arow + mi*16)*SMH + kk2 + aoffw) * 4));
        #pragma unroll
        for (int p = 0; p < 2; p++)
            ldsm4(b[p][0], b[p][1], b[p][2], b[p][3],
                  Bu + (unsigned)(((bcol0 + p*16)*SMH + kk2 + boffw) * 4));
        #pragma unroll
        for (int mi = 0; mi < 4; mi++){
            mma16(acc[mi][0], a[mi], &b[0][0]);
            mma16(acc[mi][1], a[mi], &b[0][2]);
            mma16(acc[mi][2], a[mi], &b[1][0]);
            mma16(acc[mi][3], a[mi], &b[1][2]);
        }
    }
}

// ---------------- wscan body: grouped serial AXPY over fp16 slots -----------
__device__ void wscan_body(int bid, int tid, int s0, int cnt, const float* decay_p){
    const size_t n = (size_t)BB*DD*DD;
    size_t i = ((size_t)bid*256 + tid)*8;
    if (i >= n) return;
    float gamma = 1.f/(1.f+expf(-decay_p[0]));
    float gC = expf(128.f*logf(gamma));
    uint4 pv = *(const uint4*)(g_Wbh + (size_t)(s0-1)*n + i);
    float2 p[4];
    p[0] = __half22float2(*(__half2*)&pv.x);
    p[1] = __half22float2(*(__half2*)&pv.y);
    p[2] = __half22float2(*(__half2*)&pv.z);
    p[3] = __half22float2(*(__half2*)&pv.w);
    for (int j = 0; j < cnt; j++){
        uint4* cur = (uint4*)(g_Wbh + (size_t)(s0+j)*n + i);
        uint4 cv = *cur;
        float2 c[4];
        c[0] = __half22float2(*(__half2*)&cv.x);
        c[1] = __half22float2(*(__half2*)&cv.y);
        c[2] = __half22float2(*(__half2*)&cv.z);
        c[3] = __half22float2(*(__half2*)&cv.w);
        #pragma unroll
        for (int q = 0; q < 4; q++){ c[q].x += gC*p[q].x; c[q].y += gC*p[q].y; p[q] = c[q]; }
        *(__half2*)&cv.x = __floats2half2_rn(c[0].x, c[0].y);
        *(__half2*)&cv.y = __floats2half2_rn(c[1].x, c[1].y);
        *(__half2*)&cv.z = __floats2half2_rn(c[2].x, c[2].y);
        *(__half2*)&cv.w = __floats2half2_rn(c[3].x, c[3].y);
        *cur = cv;
    }
}

// ---------------- s_batch body: masked rescaled S (fp16) --------------------
__device__ void s_batch_body(unsigned* As0, unsigned* Bs0, int z, int tid,
                             const float* decay_p){
    int b = z/NCH, n = z%NCH;
    int lane = tid&31, warp = tid>>5, wm = warp>>2, wn = warp&3;
    float acc[4][4][4];
    #pragma unroll
    for (int i=0;i<4;i++)
        #pragma unroll
        for(int j=0;j<4;j++)
            #pragma unroll
            for(int q=0;q<4;q++) acc[i][j][q]=0.f;

    const __half* rb = g_oh + ((size_t)b*TT + (size_t)n*CH)*DD;
    const __half* kb = rb - DD;
    bool z0 = (n == 0);

    auto ldb = [&](unsigned* S, int k0){
        unsigned sb = smem_u32(S);
        #pragma unroll
        for (int s = 0; s < 2; s++){
            int q = tid + 256*s; int r = q>>2, kc8 = (q&3)<<3;
            if (z0 && r == 0){
                *(uint4*)(S + r*SMH + (kc8>>1)) = make_uint4(0,0,0,0);
            } else {
                cpa16(sb + (unsigned)(r*SMH + (kc8>>1))*4u, kb + (size_t)r*DD + k0 + kc8);
            }
        }
    };

    ldh(As0, rb, DD, tid);
    ldb(Bs0, 0);
    asm volatile("cp.async.commit_group;" ::: "memory");
    int nk = DD >> 5;
    for (int t = 0; t < nk; t++){
        int cur = t & 1;
        if (t + 1 < nk){
            ldh(As0 + (cur^1)*128*SMH, rb + (t+1)*32, DD, tid);
            ldb(Bs0 + (cur^1)*128*SMH, (t+1)*32);
            asm volatile("cp.async.commit_group;" ::: "memory");
            asm volatile("cp.async.wait_group 1;" ::: "memory");
        } else {
            asm volatile("cp.async.wait_group 0;" ::: "memory");
        }
        __syncthreads();
        mma_tile_h(smem_u32(As0 + cur*128*SMH), smem_u32(Bs0 + cur*128*SMH),
                   acc, lane, wm, wn);
        __syncthreads();
    }

    float gamma = 1.f/(1.f+expf(-decay_p[0]));
    float lg = logf(gamma);
    __half* smb = g_SMh + ((size_t)b*NCH + n)*CH*CH;
    int tg=lane&3, gid=lane>>2;
    #pragma unroll
    for (int mi=0;mi<4;mi++){
        int c0r = wm*64 + mi*16 + gid;
        float sc0 = expf((float)(c0r - 128)*lg);
        float sc1 = expf((float)(c0r - 120)*lg);
        #pragma unroll
        for (int ni=0;ni<4;ni++){
            int e0c = wn*32 + ni*8 + 2*tg;
            float v0 = (c0r   > e0c  ) ? sc0*acc[mi][ni][0] : 0.f;
            float v1 = (c0r   > e0c+1) ? sc0*acc[mi][ni][1] : 0.f;
            float v2 = (c0r+8 > e0c  ) ? sc1*acc[mi][ni][2] : 0.f;
            float v3 = (c0r+8 > e0c+1) ? sc1*acc[mi][ni][3] : 0.f;
            *(__half2*)(smb + (size_t)c0r*CH + e0c)     = __floats2half2_rn(v0, v1);
            *(__half2*)(smb + (size_t)(c0r+8)*CH + e0c) = __floats2half2_rn(v2, v3);
        }
    }
}

// ---------------- intra body: reads = SM' @ vTs^T (fp16, dual store) --------
__device__ void intra_body(unsigned* As0, unsigned* Bs0, int z, int bn, int tid){
    int b = z/NCH, n = z%NCH;
    int lane = tid&31, warp = tid>>5, wm = warp>>2, wn = warp&3;
    float acc[4][4][4];
    #pragma unroll
    for (int i=0;i<4;i++)
        #pragma unroll
        for(int j=0;j<4;j++)
            #pragma unroll
            for(int q=0;q<4;q++) acc[i][j][q]=0.f;

    const __half* Ag = g_SMh + ((size_t)b*NCH + n)*CH*CH;
    const __half* Bg = g_vTs + ((size_t)b*DD + bn)*TT + (size_t)n*CH;

    ldh(As0, Ag, CH, tid);
    ldh(Bs0, Bg, TT, tid);
    asm volatile("cp.async.commit_group;" ::: "memory");
    const int nk = CH >> 5;   // 4
    for (int t = 0; t < nk; t++){
        int cur = t & 1;
        if (t + 1 < nk){
            ldh(As0 + (cur^1)*128*SMH, Ag + (t+1)*32, CH, tid);
            ldh(Bs0 + (cur^1)*128*SMH, Bg + (t+1)*32, TT, tid);
            asm volatile("cp.async.commit_group;" ::: "memory");
            asm volatile("cp.async.wait_group 1;" ::: "memory");
        } else {
            asm volatile("cp.async.wait_group 0;" ::: "memory");
        }
        __syncthreads();
        mma_tile_h(smem_u32(As0 + cur*128*SMH), smem_u32(Bs0 + cur*128*SMH),
                   acc, lane, wm, wn);
        __syncthreads();
    }

    size_t ob = ((size_t)b*TT + (size_t)n*CH)*DD + bn;
    int tg=lane&3, gid=lane>>2;
    #pragma unroll
    for (int mi=0;mi<4;mi++){
        #pragma unroll
        for (int ni=0;ni<4;ni++){
            int row = wm*64 + mi*16 + gid;
            int col = wn*32 + ni*8 + 2*tg;
            size_t i0 = ob + (size_t)row*DD + col;
            size_t i1 = ob + (size_t)(row+8)*DD + col;
            *(float2*)(g_reads+i0) = make_float2(acc[mi][ni][0], acc[mi][ni][1]);
            *(float2*)(g_reads+i1) = make_float2(acc[mi][ni][2], acc[mi][ni][3]);
            *(__half2*)(g_readsh+i0) = __floats2half2_rn(acc[mi][ni][0], acc[mi][ni][1]);
            *(__half2*)(g_readsh+i1) = __floats2half2_rn(acc[mi][ni][2], acc[mi][ni][3]);
        }
    }
}

// ---------------- combined launches: scan GEMMs hidden under wscan ----------
__global__ void __launch_bounds__(256)
wscan_sbatch_k(const float* __restrict__ decay_p){
    __shared__ unsigned As[2*128*SMH], Bs[2*128*SMH];
    int tid = threadIdx.x;
    if ((int)blockIdx.x < BB*NCH)
        s_batch_body(As, Bs, blockIdx.x, tid, decay_p);
    else
        wscan_body(blockIdx.x - BB*NCH, tid, 1, 8, decay_p);
}
__global__ void __launch_bounds__(256)
wscan_intra_k(const float* __restrict__ decay_p){
    __shared__ unsigned As[2*128*SMH], Bs[2*128*SMH];
    int tid = threadIdx.x;
    if ((int)blockIdx.x < 6*BB*NCH){
        int q = blockIdx.x;
        intra_body(As, Bs, q/6, (q%6)*128, tid);
    } else {
        wscan_body(blockIdx.x - 6*BB*NCH, tid, 9, 8, decay_p);
    }
}
__global__ void wscan_h(int s0, int cnt, const float* __restrict__ decay_p){
    wscan_body(blockIdx.x, threadIdx.x, s0, cnt, decay_p);
}

// ---------------- u_batch (standalone, fp16 GEMM) ---------------------------
__global__ void __launch_bounds__(256)
u_batch_h(){
    __shared__ unsigned As[2][128*SMH], Bs[2][128*SMH];
    int z = blockIdx.z, b = z/(NCH-1), mch = z%(NCH-1);
    int bm = blockIdx.y*128, bn = blockIdx.x*128;
    int tid = threadIdx.x, lane = tid&31, warp = tid>>5;
    int wm = warp>>2, wn = warp&3;
    float acc[4][4][4];
    #pragma unroll
    for (int i=0;i<4;i++)
        #pragma unroll
        for(int j=0;j<4;j++)
            #pragma unroll
            for(int q=0;q<4;q++) acc[i][j][q]=0.f;

    const __half* Ag = g_vTs + ((size_t)b*DD + bm)*TT + (size_t)mch*CH;
    const __half* Bg = g_kT  + ((size_t)b*DD + bn)*TT + (size_t)mch*CH;

    ldh(As[0], Ag, TT, tid);
    ldh(Bs[0], Bg, TT, tid);
    asm volatile("cp.async.commit_group;" ::: "memory");
    const int nk = CH >> 5;
    for (int t = 0; t < nk; t++){
        int cur = t & 1;
        if (t + 1 < nk){
            ldh(As[cur^1], Ag + (t+1)*32, TT, tid);
            ldh(Bs[cur^1], Bg + (t+1)*32, TT, tid);
            asm volatile("cp.async.commit_group;" ::: "memory");
            asm volatile("cp.async.wait_group 1;" ::: "memory");
        } else {
            asm volatile("cp.async.wait_group 0;" ::: "memory");
        }
        __syncthreads();
        mma_tile_h(smem_u32(As[cur]), smem_u32(Bs[cur]), acc, lane, wm, wn);
        __syncthreads();
    }

    __half* Wout = g_Wbh + ((size_t)mch*BB + b)*(size_t)DD*DD;
    int tg = lane&3, gid = lane>>2;
    #pragma unroll
    for (int mi=0;mi<4;mi++){
        #pragma unroll
        for (int ni=0;ni<4;ni++){
            int row = bm + wm*64 + mi*16 + gid;
            int col = bn + wn*32 + ni*8 + 2*tg;
            *(__half2*)(Wout + (size_t)row*DD + col)     = __floats2half2_rn(acc[mi][ni][0], acc[mi][ni][1]);
            *(__half2*)(Wout + (size_t)(row+8)*DD + col) = __floats2half2_rn(acc[mi][ni][2], acc[mi][ni][3]);
        }
    }
}

// ---------------- transpose: build vT (gw-scaled) and shifted-keys^T --------
__global__ void tpose_k(const float* __restrict__ decay_p){
    __shared__ float s1[32][33], s2[32][33];
    int b = blockIdx.z, d0 = blockIdx.y*32, t0 = blockIdx.x*32;
    int tx = threadIdx.x, ty = threadIdx.y;      // 32 x 8
    float gamma = 1.f/(1.f+expf(-decay_p[0]));
    float lg = logf(gamma);
    const __half* vb = g_vh + (size_t)b*TT*DD;
    const __half* ob = g_oh + (size_t)b*TT*DD;
    #pragma unroll
    for (int i = 0; i < 4; i++){
        int tl = ty + 8*i;
        int t = t0 + tl;
        float gw = expf((float)(CH-1-(t&(CH-1)))*lg);
        s1[tl][tx] = __half2float(vb[(size_t)t*DD + d0 + tx]) * gw;
        s2[tl][tx] = (t == 0) ? 0.f : __half2float(ob[(size_t)(t-1)*DD + d0 + tx]);
    }
    __syncthreads();
    __half* vT = g_vTs + (size_t)b*DD*TT;
    __half* kT = g_kT  + (size_t)b*DD*TT;
    #pragma unroll
    for (int i = 0; i < 4; i++){
        int dl = ty + 8*i;
        vT[(size_t)(d0+dl)*TT + t0 + tx] = __float2half_rn(s1[tx][dl]);
        kT[(size_t)(d0+dl)*TT + t0 + tx] = __float2half_rn(s2[tx][dl]);
    }
}

// ---------------- rmsnorm (half out) ----------------------------------------
__global__ void rmsnorm_k(const float* __restrict__ x, const float* __restrict__ w) {
    int row = blockIdx.x;
    const float* xr = x + (size_t)row*DD;
    __half* o = g_xnh + (size_t)row*DD;
    float s = 0.f;
    for (int d = threadIdx.x; d < DD; d += blockDim.x) { float v = xr[d]; s += v*v; }
    __shared__ float red[32];
    for (int off = 16; off; off >>= 1) s += __shfl_down_sync(0xffffffffu, s, off);
    if ((threadIdx.x & 31) == 0) red[threadIdx.x >> 5] = s;
    __syncthreads();
    if (threadIdx.x < 32) {
        float t = (threadIdx.x < (blockDim.x >> 5)) ? red[threadIdx.x] : 0.f;
        for (int off = 16; off; off >>= 1) t += __shfl_down_sync(0xffffffffu, t, off);
        if (threadIdx.x == 0) red[0] = t;
    }
    __syncthreads();
    float scale = rsqrtf(red[0] / (float)DD + EPS);
    for (int d = threadIdx.x; d < DD; d += blockDim.x)
        o[d] = __float2half_rn(xr[d] * scale * w[d]);
}

// ---------------- single-launch weight convert (all 5 weights -> g_wth) -----
__global__ void prep_k(const float* __restrict__ w0, const float* __restrict__ w1,
                       const float* __restrict__ w2, const float* __restrict__ w3,
                       const float* __restrict__ w4){
    long i = (long)blockIdx.x*256 + threadIdx.x;
    if (i >= 1179648) return;
    const float* src;
    long loc = i;
    if (i < 294912){ src = w0; }
    else if (i < 589824){ src = w1; loc = i - 294912; }
    else if (i < 884736){ src = w2; loc = i - 589824; }
    else if (i < 1032192){ src = w3; loc = i - 884736; }
    else { src = w4; loc = i - 1032192; }
    float4 v = ((const float4*)src)[loc];
    ((__half2*)g_wth)[2*i]   = __floats2half2_rn(v.x, v.y);
    ((__half2*)g_wth)[2*i+1] = __floats2half2_rn(v.z, v.w);
}

// ---------------- conv + gate: register-tiled, 8 ch x 4 l per thread --------
__global__ void __launch_bounds__(256)
conv_gate_k(const float* __restrict__ cw, const float* __restrict__ cb) {
    long j = (long)blockIdx.x*256 + threadIdx.x;       // 8*1024*192 threads
    const long NTH = (long)BB*(TT/4)*(DI/8);
    if (j >= NTH) return;
    int e8 = (int)(j % (DI/8));
    long t2 = j / (DI/8);
    int l4 = (int)(t2 % (TT/4));
    int b  = (int)(t2 / (TT/4));
    int l0 = l4*4, e = e8*8;

    // conv weights: 8 channels x 4 taps (contiguous 32 floats), bias 8
    float w[8][4];
    #pragma unroll
    for (int c = 0; c < 8; c += 2){
        float4 a = *(const float4*)(cw + (e+c)*4);
        float4 bq = *(const float4*)(cw + (e+c+1)*4);
        w[c][0]=a.x; w[c][1]=a.y; w[c][2]=a.z; w[c][3]=a.w;
        w[c+1][0]=bq.x; w[c+1][1]=bq.y; w[c+1][2]=bq.z; w[c+1][3]=bq.w;
    }
    float4 cb0 = *(const float4*)(cb + e);
    float4 cb1 = *(const float4*)(cb + e + 4);
    float bias[8] = {cb0.x,cb0.y,cb0.z,cb0.w,cb1.x,cb1.y,cb1.z,cb1.w};

    // input rows l0-3 .. l0+3 (7 rows of 8 halfs)
    const __half* base = g_pgh + ((size_t)b*TT + l0)*(2*DI) + e;
    uint4 r[7];
    #pragma unroll
    for (int i = 0; i < 7; i++){
        int ll = l0 - 3 + i;
        if (ll >= 0) r[i] = *(const uint4*)(base + (long)(i-3)*(2*DI));
        else         r[i] = make_uint4(0,0,0,0);
    }

    __half* up = g_uh + ((size_t)b*TT + l0)*DI + e;
    #pragma unroll
    for (int jo = 0; jo < 4; jo++){
        float ac[8];
        #pragma unroll
        for (int c = 0; c < 8; c++) ac[c] = bias[c];
        #pragma unroll
        for (int jj = 0; jj < 4; jj++){
            uint4 rv = r[jo + jj];
            const __half2* h = (const __half2*)&rv;
            #pragma unroll
            for (int p = 0; p < 4; p++){
                float2 f = __half22float2(h[p]);
                ac[2*p]   += f.x * w[2*p][jj];
                ac[2*p+1] += f.y * w[2*p+1][jj];
            }
        }
        uint4 gv = *(const uint4*)(base + (long)jo*(2*DI) + DI);
        const __half2* gh = (const __half2*)&gv;
        uint4 outv;
        __half2* oh2 = (__half2*)&outv;
        #pragma unroll
        for (int p = 0; p < 4; p++){
            float2 g = __half22float2(gh[p]);
            float r0 = (ac[2*p]  /(1.f+expf(-ac[2*p])))   * (g.x/(1.f+expf(-g.x)));
            float r1 = (ac[2*p+1]/(1.f+expf(-ac[2*p+1]))) * (g.y/(1.f+expf(-g.y)));
            oh2[p] = __floats2half2_rn(r0, r1);
        }
        *(uint4*)(up + (long)jo*DI) = outv;
    }
}

// ---------------- launch ----------------------------------------------------
extern "C" void kernel_launch(void* const* d_in, const int* in_sizes, int n_in,
                              void* d_out, int out_size) {
    const float* x          = (const float*)d_in[0];
    const float* norm_w     = (const float*)d_in[1];
    const float* proj_w     = (const float*)d_in[2];
    const float* gate_w     = (const float*)d_in[3];
    const float* conv_w     = (const float*)d_in[4];
    const float* conv_b     = (const float*)d_in[5];
    const float* out_proj_w = (const float*)d_in[6];
    const float* write_w    = (const float*)d_in[7];
    const float* read_w     = (const float*)d_in[8];
    const float* decay      = (const float*)d_in[9];
    const float* log_alpha  = (const float*)d_in[10];
    float* out = (float*)d_out;

    __half *xnh, *pgh, *uh, *oh, *vh, *readsh, *wth, *wbh;
    float *o, *reads;
    cudaGetSymbolAddress((void**)&xnh,    g_xnh);
    cudaGetSymbolAddress((void**)&pgh,    g_pgh);
    cudaGetSymbolAddress((void**)&uh,     g_uh);
    cudaGetSymbolAddress((void**)&oh,     g_oh);
    cudaGetSymbolAddress((void**)&vh,     g_vh);
    cudaGetSymbolAddress((void**)&readsh, g_readsh);
    cudaGetSymbolAddress((void**)&wth,    g_wth);
    cudaGetSymbolAddress((void**)&wbh,    g_Wbh);
    cudaGetSymbolAddress((void**)&o,      g_out);
    cudaGetSymbolAddress((void**)&reads,  g_reads);

    cudaFuncSetAttribute(gemm_h<1>, cudaFuncAttributeMaxDynamicSharedMemorySize, DSM_BYTES);
    cudaFuncSetAttribute(gemm_h<2>, cudaFuncAttributeMaxDynamicSharedMemorySize, DSM_BYTES);
    cudaFuncSetAttribute(gemm_h<5>, cudaFuncAttributeMaxDynamicSharedMemorySize, DSM_BYTES);
    cudaFuncSetAttribute(gemm_h<6>, cudaFuncAttributeMaxDynamicSharedMemorySize, DSM_BYTES);

    // 0: all weight converts in one launch; 1: rmsnorm
    prep_k<<<(1179648+255)/256, 256>>>(proj_w, gate_w, out_proj_w, write_w, read_w);
    rmsnorm_k<<<BT, 256>>>(x, norm_w);
    // 2: fused proj+gate GEMM (N=3072)
    gemm_h<5><<<dim3(2*DI/128, BT/128), 256, DSM_BYTES>>>(
        xnh, wth + W_PROJ, nullptr, pgh, DD, 2*DI, nullptr, nullptr, nullptr);
    // 3: conv + gate (register-tiled) -> profiled launch
    conv_gate_k<<<(unsigned)(((long)BB*(TT/4)*(DI/8) + 255)/256), 256>>>(conv_w, conv_b);
    // out projection (dual store) + write projection (fp16)
    dim3 g2(DD/128, BT/128);
    gemm_h<6><<<g2, 256, DSM_BYTES>>>(uh, wth + W_OUTP, o, oh, DI, DD, nullptr, nullptr, nullptr);
    gemm_h<5><<<g2, 256, DSM_BYTES>>>(oh, wth + W_WRIT, nullptr, vh, DD, DD, nullptr, nullptr, nullptr);
    // transpose, chunk outer products
    tpose_k<<<dim3(TT/32, DD/32, BB), dim3(32,8)>>>(decay);
    u_batch_h<<<dim3(6,6,BB*(NCH-1)), 256>>>();
    // scan: s_batch hidden under wscan group 1, intra hidden under group 2
    wscan_sbatch_k<<<BB*NCH + WSB, 256>>>(decay);     // s_batch + slots 1-8
    wscan_intra_k<<<6*BB*NCH + WSB, 256>>>(decay);    // intra  + slots 9-16
    wscan_h<<<WSB, 256>>>(17, 8, decay);              // slots 17-24
    wscan_h<<<WSB, 256>>>(25, 6, decay);              // slots 25-30
    // inter reads (fp16, accumulate into reads)
    gemm_h<2><<<dim3(6,1,BB*(NCH-1)), 256, DSM_BYTES>>>(oh, wbh, reads, readsh, DD, DD, nullptr, nullptr, decay);
    // final: out = x + o + alpha*(reads @ read_w^T)
    gemm_h<1><<<g2, 256, DSM_BYTES>>>(readsh, wth + W_READ, out, nullptr, DD, DD, x, o, log_alpha);
}